// round 12
// baseline (speedup 1.0000x reference)
#include <cuda_runtime.h>
#include <cuda_fp16.h>
#include <math.h>
#include <stdint.h>

#define NR 8192
#define D  512
#define SCALEF 0.1f

__device__ __half g_Eh[(size_t)NR * NR];     // 128 MB: E fp16, k-word-permuted columns
__device__ __half g_xnh[(size_t)NR * D];     // normalized x fp16, permuted features
__device__ __half g_xth[(size_t)D * NR];     // x^T fp16 [512][8192], permuted columns
__device__ float  g_xneg[(size_t)NR * D];
__device__ float  g_invr[NR];                // natural order
__device__ float  g_invr_p[NR];              // stored(half)-position order

// word-level perm within 8-word (16-half) groups: stored word p holds logical word
// l(p) = (p>>1) + 4*(p&1); inverse: logical w stored at 2*(w&3) + (w>>2)
__device__ __host__ __forceinline__ int lword(int p) { return (p >> 1) + 4 * (p & 1); }

#define ROWW 40                   // smem row stride in 32-bit words (rows hold 32 data words)
#define A_TILE_W (128 * ROWW)     // 5120
#define B_TILE_W (256 * ROWW)     // 10240
#define STAGE_W  (A_TILE_W + B_TILE_W)     // 15360 words
#define NSTAGE 3
#define SMEM_BYTES (NSTAGE * STAGE_W * 4)  // 184320 (gemm1)

// gemm2: 64x256 tiles, 2-stage, 2 CTAs/SM
#define G2_A_TILE_W (64 * ROWW)             // 2560
#define G2_B_TILE_W (256 * ROWW)            // 10240
#define G2_STAGE_W  (G2_A_TILE_W + G2_B_TILE_W)  // 12800
#define G2_SMEM_BYTES (2 * G2_STAGE_W * 4)  // 102400

__device__ __forceinline__ float warpReduceSum(float v) {
#pragma unroll
    for (int o = 16; o > 0; o >>= 1) v += __shfl_xor_sync(0xffffffffu, v, o);
    return v;
}
__device__ __forceinline__ uint32_t smem_u32(const void* p) {
    uint32_t a;
    asm("{ .reg .u64 t; cvta.to.shared.u64 t, %1; cvt.u32.u64 %0, t; }" : "=r"(a) : "l"(p));
    return a;
}
__device__ __forceinline__ void cp16(uint32_t s, const void* g) {
    asm volatile("cp.async.cg.shared.global [%0], [%1], 16;" :: "r"(s), "l"(g));
}
#define CP_COMMIT() asm volatile("cp.async.commit_group;")
#define CP_WAIT1()  asm volatile("cp.async.wait_group 1;")
#define CP_WAIT0()  asm volatile("cp.async.wait_group 0;")

__device__ __forceinline__ void mma_f16(float* c, uint32_t a0, uint32_t a1, uint32_t a2,
                                        uint32_t a3, uint32_t b0, uint32_t b1) {
    asm volatile(
        "mma.sync.aligned.m16n8k16.row.col.f32.f16.f16.f32 "
        "{%0,%1,%2,%3}, {%4,%5,%6,%7}, {%8,%9}, {%0,%1,%2,%3};"
        : "+f"(c[0]), "+f"(c[1]), "+f"(c[2]), "+f"(c[3])
        : "r"(a0), "r"(a1), "r"(a2), "r"(a3), "r"(b0), "r"(b1));
}

// ---------------- fused prep (rows) + transpose, one launch ----------------
// blocks [0,4096): L2-normalize 2 rows each -> g_xnh (word-permuted)
// blocks [4096,8192): 32x32 transpose tile -> g_xth (permuted k columns)
__global__ void prep_trans_kernel(const float* __restrict__ x) {
    int b = blockIdx.x;
    int t = threadIdx.x;  // 256
    if (b < 4096) {
        __shared__ float sred[8];
        int row = 2 * b + (t >> 7);
        int tt = t & 127;
        float4 a = ((const float4*)(x + (size_t)row * D))[tt];
        float ss = a.x * a.x + a.y * a.y + a.z * a.z + a.w * a.w;
        ss = warpReduceSum(ss);
        if ((t & 31) == 0) sred[t >> 5] = ss;
        __syncthreads();
        int base = (t >> 7) * 4;
        float tot = sred[base] + sred[base + 1] + sred[base + 2] + sred[base + 3];
        float inv = 1.0f / fmaxf(sqrtf(tot), 1e-12f);
        float v[4] = {a.x * inv, a.y * inv, a.z * inv, a.w * inv};
        __half2* dst = (__half2*)(g_xnh + (size_t)row * D);
#pragma unroll
        for (int e = 0; e < 2; e++) {
            int w = 2 * tt + e;  // logical word
            int wg = w & 7;
            int sp = (w & ~7) | (2 * (wg & 3) + (wg >> 2));
            dst[sp] = __floats2half2_rn(v[2 * e], v[2 * e + 1]);
        }
    } else {
        __shared__ float tl[32][33];
        int id = b - 4096;
        int k0 = (id & 255) * 32, n0 = (id >> 8) * 32;
        int tx = t & 31, ty = t >> 5;  // 32 x 8
#pragma unroll
        for (int r = 0; r < 32; r += 8)
            tl[ty + r][tx] = x[(size_t)(k0 + ty + r) * D + n0 + tx];
        __syncthreads();
        int pw = (tx >> 1) & 7;
        int lh = (tx & ~15) | (2 * lword(pw) + (tx & 1));
#pragma unroll
        for (int r = 0; r < 32; r += 8)
            g_xth[(size_t)(n0 + ty + r) * NR + k0 + tx] = __float2half_rn(tl[lh][ty + r]);
    }
}

// ============== GEMM1: E = exp(xn @ xn^T - 1) fp16, 128x256 tiles, mirror ==============
__global__ void __launch_bounds__(256, 1) gemm1_kernel() {
    // decode block: for each bj (0..31), bi in [0, min(64, 2bj+2))
    int kid = blockIdx.x, bj = 0;
    for (;;) {
        int cnum = min(64, 2 * bj + 2);
        if (kid < cnum) break;
        kid -= cnum; bj++;
    }
    int bi = kid;
    const int I0 = bi * 128, J0 = bj * 256;

    extern __shared__ uint32_t su[];
    uint32_t sbase = smem_u32(su);
    int t = threadIdx.x, wid = t >> 5, lane = t & 31;
    int g = lane >> 2, tq = lane & 3;
    int warpM = (wid >> 2) * 64, warpN = (wid & 3) * 64;

    const __half* aG = g_xnh + (size_t)(I0 + (t >> 1)) * D + (t & 1) * 32;
    const __half* bG = g_xnh + (size_t)(J0 + t) * D;
    uint32_t dstA = sbase + (uint32_t)((t >> 1) * ROWW + (t & 1) * 16) * 4;
    uint32_t dstB = sbase + (uint32_t)(A_TILE_W + t * ROWW) * 4;

    auto copy_stage = [&](int stage, int k0) {
        uint32_t off = (uint32_t)(stage * STAGE_W) * 4;
#pragma unroll
        for (int q = 0; q < 4; q++) cp16(dstA + off + q * 16, aG + k0 + q * 8);
#pragma unroll
        for (int q = 0; q < 8; q++) cp16(dstB + off + q * 16, bG + k0 + q * 8);
        CP_COMMIT();
    };

    float acc[4][8][4];
#pragma unroll
    for (int i = 0; i < 4; i++)
#pragma unroll
        for (int j = 0; j < 8; j++)
#pragma unroll
            for (int q = 0; q < 4; q++) acc[i][j][q] = 0.f;

    const int C = D / 64;  // 8 chunks
    copy_stage(0, 0);
    copy_stage(1, 64);

    int stage = 0;
    for (int c = 0; c < C; c++) {
        if (c + 2 < C) CP_WAIT1(); else CP_WAIT0();
        __syncthreads();
        if (c + 2 < C) {
            int ns = stage + 2; if (ns >= NSTAGE) ns -= NSTAGE;
            copy_stage(ns, (c + 2) * 64);
        }
        const uint32_t* sA = su + stage * STAGE_W;
        const uint32_t* sB = sA + A_TILE_W;
#pragma unroll
        for (int s = 0; s < 4; s++) {  // 4 k16 steps per 64-half chunk
            uint32_t af[4][4], bf[8][2];
#pragma unroll
            for (int i = 0; i < 4; i++) {
                const uint32_t* pa = sA + (warpM + i * 16 + g) * ROWW + 8 * s + 2 * tq;
                uint2 lo = *(const uint2*)pa;              // (a0, a2)
                uint2 hi = *(const uint2*)(pa + 8 * ROWW); // (a1, a3)
                af[i][0] = lo.x; af[i][1] = hi.x; af[i][2] = lo.y; af[i][3] = hi.y;
            }
#pragma unroll
            for (int j = 0; j < 8; j++) {
                uint2 b = *(const uint2*)(sB + (warpN + j * 8 + g) * ROWW + 8 * s + 2 * tq);
                bf[j][0] = b.x; bf[j][1] = b.y;
            }
#pragma unroll
            for (int i = 0; i < 4; i++)
#pragma unroll
                for (int j = 0; j < 8; j++)
                    mma_f16(acc[i][j], af[i][0], af[i][1], af[i][2], af[i][3],
                            bf[j][0], bf[j][1]);
        }
        if (++stage >= NSTAGE) stage = 0;
    }
    __syncthreads();

    // ---- epilogue: exp(s-1) -> eb_w[128][131] half2 words -> permuted fp16 writes ----
    const int EBW = 131;
    uint32_t* eb = su;
#pragma unroll
    for (int i = 0; i < 4; i++)
#pragma unroll
        for (int j = 0; j < 8; j++) {
            int r0 = warpM + i * 16 + g;
            int wrd = ((warpN + j * 8) >> 1) + tq;
            __half2 lo = __floats2half2_rn(__expf(acc[i][j][0] - 1.0f), __expf(acc[i][j][1] - 1.0f));
            __half2 hi = __floats2half2_rn(__expf(acc[i][j][2] - 1.0f), __expf(acc[i][j][3] - 1.0f));
            eb[r0 * EBW + wrd]       = *(uint32_t*)&lo;
            eb[(r0 + 8) * EBW + wrd] = *(uint32_t*)&hi;
        }
    __syncthreads();

    // natural: rows I0+r, stored cols J0..: warp wid covers rows wid*16..+15
    {
        int b = 8 * (lane >> 1) + 2 * (lane & 1);
#pragma unroll 1
        for (int it = 0; it < 16; it++) {
            int r = wid * 16 + it;
            const uint32_t* src = eb + r * EBW;
            uint4 v = make_uint4(src[b], src[b + 4], src[b + 1], src[b + 5]);
            *(uint4*)(g_Eh + (size_t)(I0 + r) * NR + J0 + 8 * lane) = v;
        }
    }
    // mirror: rows J0+cc, stored cols I0..: warp covers rows wid*32..+31
    {
        int w = 8 * (lane >> 2) + (lane & 3);
        int r0 = 2 * w;
#pragma unroll 1
        for (int it = 0; it < 32; it++) {
            int cc = wid * 32 + it;
            int cw = cc >> 1, ch = (cc & 1) * 16;
            uint32_t h0 = (eb[(r0)     * EBW + cw] >> ch) & 0xffffu;
            uint32_t h1 = (eb[(r0 + 1) * EBW + cw] >> ch) & 0xffffu;
            uint32_t h2 = (eb[(r0 + 8) * EBW + cw] >> ch) & 0xffffu;
            uint32_t h3 = (eb[(r0 + 9) * EBW + cw] >> ch) & 0xffffu;
            uint2 v = make_uint2(h0 | (h1 << 16), h2 | (h3 << 16));
            *(uint2*)(g_Eh + (size_t)(J0 + cc) * NR + I0 + 4 * lane) = v;
        }
    }
}

// ---------------- row sums of fp16 E -> invr (+ fused permuted copy) ----------------
__global__ void rowsum_kernel() {
    __shared__ float sred[8];
    int row = blockIdx.x, t = threadIdx.x;  // 256 threads
    const uint4* e = (const uint4*)(g_Eh + (size_t)row * NR);
    float s = 0.f;
#pragma unroll
    for (int i = 0; i < 4; i++) {
        uint4 v = e[t + 256 * i];
        const __half2* hp = (const __half2*)&v;
#pragma unroll
        for (int k = 0; k < 4; k++) {
            float2 f = __half22float2(hp[k]);
            s += f.x + f.y;
        }
    }
    s = warpReduceSum(s);
    if ((t & 31) == 0) sred[t >> 5] = s;
    __syncthreads();
    if (t == 0) {
        float tot = 0.f;
#pragma unroll
        for (int i = 0; i < 8; i++) tot += sred[i];
        float inv = 1.0f / tot;
        g_invr[row] = inv;
        int w = (row >> 1) & 7, e2 = row & 1;
        int sp = (row & ~15) | (2 * (2 * (w & 3) + (w >> 2)) + e2);
        g_invr_p[sp] = inv;
    }
}

// ============== GEMM2: xneg = [E*(invr_i+invr_k)] @ x, 64x256 tiles, 2 CTA/SM ==============
__global__ void __launch_bounds__(256, 2) gemm2_kernel() {
    const int n0 = blockIdx.x * 256;  // 0..1
    const int I0 = blockIdx.y * 64;   // 0..127

    extern __shared__ uint32_t su[];
    uint32_t sbase = smem_u32(su);
    int t = threadIdx.x, wid = t >> 5, lane = t & 31;
    int g = lane >> 2, tq = lane & 3;
    int warpM = (wid >> 2) * 32, warpN = (wid & 3) * 64;

    int arow = t >> 2, aseg = (t & 3) * 16;  // 4 threads/row, 16 halves each
    const float ri = g_invr[I0 + arow];
    const __half* aG = g_Eh + (size_t)(I0 + arow) * NR + aseg;
    const __half* bG = g_xth + (size_t)(n0 + t) * NR;
    uint32_t stsA = sbase + (uint32_t)(arow * ROWW + (t & 3) * 8) * 4;
    uint32_t dstB = sbase + (uint32_t)(G2_A_TILE_W + t * ROWW) * 4;

    uint4 pa[2];
    auto ldgA = [&](int k0) {
#pragma unroll
        for (int q = 0; q < 2; q++) pa[q] = ((const uint4*)(aG + k0))[q];
    };
    auto stsA_f = [&](int stg, int k0) {
        const float* rp = g_invr_p + k0 + aseg;
        uint32_t dst = stsA + (uint32_t)(stg * G2_STAGE_W) * 4;
#pragma unroll
        for (int q = 0; q < 2; q++) {
            float4 r0 = __ldg((const float4*)(rp + q * 8));
            float4 r1 = __ldg((const float4*)(rp + q * 8 + 4));
            const __half2* hp = (const __half2*)&pa[q];
            float2 f0 = __half22float2(hp[0]);
            float2 f1 = __half22float2(hp[1]);
            float2 f2 = __half22float2(hp[2]);
            float2 f3 = __half22float2(hp[3]);
            __half2 o0 = __floats2half2_rn(f0.x * (ri + r0.x), f0.y * (ri + r0.y));
            __half2 o1 = __floats2half2_rn(f1.x * (ri + r0.z), f1.y * (ri + r0.w));
            __half2 o2 = __floats2half2_rn(f2.x * (ri + r1.x), f2.y * (ri + r1.y));
            __half2 o3 = __floats2half2_rn(f3.x * (ri + r1.z), f3.y * (ri + r1.w));
            asm volatile("st.shared.v4.b32 [%0], {%1,%2,%3,%4};"
                         :: "r"(dst + q * 16), "r"(*(uint32_t*)&o0), "r"(*(uint32_t*)&o1),
                            "r"(*(uint32_t*)&o2), "r"(*(uint32_t*)&o3));
        }
    };
    auto cpB = [&](int stg, int k0) {
        uint32_t off = (uint32_t)(stg * G2_STAGE_W) * 4;
#pragma unroll
        for (int q = 0; q < 8; q++) cp16(dstB + off + q * 16, bG + k0 + q * 8);
        CP_COMMIT();
    };

    float acc[2][8][4];
#pragma unroll
    for (int i = 0; i < 2; i++)
#pragma unroll
        for (int j = 0; j < 8; j++)
#pragma unroll
            for (int q = 0; q < 4; q++) acc[i][j][q] = 0.f;

    const int C = NR / 64;  // 128 chunks
    ldgA(0); stsA_f(0, 0); cpB(0, 0);
    ldgA(64); stsA_f(1, 64); cpB(1, 64);
    ldgA(128);

    for (int c = 0; c < C; c++) {
        if (c + 1 < C) CP_WAIT1(); else CP_WAIT0();
        __syncthreads();
        const uint32_t* sA = su + (c & 1) * G2_STAGE_W;
        const uint32_t* sB = sA + G2_A_TILE_W;
#pragma unroll
        for (int s = 0; s < 4; s++) {
            uint32_t af[2][4], bf[8][2];
#pragma unroll
            for (int i = 0; i < 2; i++) {
                const uint32_t* p = sA + (warpM + i * 16 + g) * ROWW + 8 * s + 2 * tq;
                uint2 lo = *(const uint2*)p;
                uint2 hi = *(const uint2*)(p + 8 * ROWW);
                af[i][0] = lo.x; af[i][1] = hi.x; af[i][2] = lo.y; af[i][3] = hi.y;
            }
#pragma unroll
            for (int j = 0; j < 8; j++) {
                uint2 b = *(const uint2*)(sB + (warpN + j * 8 + g) * ROWW + 8 * s + 2 * tq);
                bf[j][0] = b.x; bf[j][1] = b.y;
            }
#pragma unroll
            for (int i = 0; i < 2; i++)
#pragma unroll
                for (int j = 0; j < 8; j++)
                    mma_f16(acc[i][j], af[i][0], af[i][1], af[i][2], af[i][3],
                            bf[j][0], bf[j][1]);
        }
        __syncthreads();
        if (c + 2 < C) {
            stsA_f(c & 1, (c + 2) * 64);   // consumes pa (chunk c+2)
            cpB(c & 1, (c + 2) * 64);
            if (c + 3 < C) ldgA((c + 3) * 64);
        }
    }

    // epilogue: f32 stores, n not permuted
#pragma unroll
    for (int i = 0; i < 2; i++)
#pragma unroll
        for (int j = 0; j < 8; j++) {
            int r0 = I0 + warpM + i * 16 + g;
            int c0 = n0 + warpN + j * 8 + 2 * tq;
            *(float2*)(g_xneg + (size_t)r0 * D + c0)       = make_float2(acc[i][j][0], acc[i][j][1]);
            *(float2*)(g_xneg + (size_t)(r0 + 8) * D + c0) = make_float2(acc[i][j][2], acc[i][j][3]);
        }
}

// ---------------- y = x - SCALE*xneg, LayerNorm ----------------
__global__ void ln_kernel(const float* __restrict__ x, const float* __restrict__ gamma,
                          const float* __restrict__ beta, float* __restrict__ out) {
    __shared__ float s1[4], s2[4];
    int row = blockIdx.x, t = threadIdx.x;  // 128 threads
    float4 xv = ((const float4*)(x + (size_t)row * D))[t];
    float4 nv = ((const float4*)(g_xneg + (size_t)row * D))[t];
    float4 y = make_float4(xv.x - SCALEF * nv.x, xv.y - SCALEF * nv.y,
                           xv.z - SCALEF * nv.z, xv.w - SCALEF * nv.w);
    float s = y.x + y.y + y.z + y.w;
    float q = y.x * y.x + y.y * y.y + y.z * y.z + y.w * y.w;
    s = warpReduceSum(s);
    q = warpReduceSum(q);
    if ((t & 31) == 0) { s1[t >> 5] = s; s2[t >> 5] = q; }
    __syncthreads();
    float sum = s1[0] + s1[1] + s1[2] + s1[3];
    float sq  = s2[0] + s2[1] + s2[2] + s2[3];
    float mean = sum * (1.0f / D);
    float var = sq * (1.0f / D) - mean * mean;
    float rstd = rsqrtf(var + 1e-6f);
    float4 gm = ((const float4*)gamma)[t];
    float4 b = ((const float4*)beta)[t];
    float4 o;
    o.x = (y.x - mean) * rstd * gm.x + b.x;
    o.y = (y.y - mean) * rstd * gm.y + b.y;
    o.z = (y.z - mean) * rstd * gm.z + b.z;
    o.w = (y.w - mean) * rstd * gm.w + b.w;
    ((float4*)out)[(size_t)row * (D / 4) + t] = o;
}

extern "C" void kernel_launch(void* const* d_in, const int* in_sizes, int n_in,
                              void* d_out, int out_size) {
    const float* x     = (const float*)d_in[0];
    const float* gamma = (const float*)d_in[1];
    const float* beta  = (const float*)d_in[2];
    float* out = (float*)d_out;

    cudaFuncSetAttribute(gemm1_kernel, cudaFuncAttributeMaxDynamicSharedMemorySize, SMEM_BYTES);
    cudaFuncSetAttribute(gemm2_kernel, cudaFuncAttributeMaxDynamicSharedMemorySize, G2_SMEM_BYTES);

    prep_trans_kernel<<<8192, 256>>>(x);
    gemm1_kernel<<<1056, 256, SMEM_BYTES>>>();
    rowsum_kernel<<<NR, 256>>>();
    gemm2_kernel<<<dim3(2, 128), 256, G2_SMEM_BYTES>>>();
    ln_kernel<<<NR, 128>>>(x, gamma, beta, out);
}

// round 13
// speedup vs baseline: 1.1683x; 1.1683x over previous
#include <cuda_runtime.h>
#include <cuda_fp16.h>
#include <math.h>
#include <stdint.h>

#define NR 8192
#define D  512
#define SCALEF 0.1f

__device__ __half g_Eh[(size_t)NR * NR];     // 128 MB: E fp16, k-word-permuted columns
__device__ __half g_xnh[(size_t)NR * D];     // normalized x fp16, permuted features
__device__ __half g_xth[(size_t)D * NR];     // x^T fp16 [512][8192], permuted columns
__device__ float  g_xneg[(size_t)NR * D];
__device__ float  g_rsum[NR];                // row sums (atomic accum in gemm1 epilogue)
__device__ float  g_invr[NR];                // natural order
__device__ float  g_invr_p[NR];              // stored(half)-position order

// word-level perm within 8-word (16-half) groups: stored word p holds logical word
// l(p) = (p>>1) + 4*(p&1); inverse: logical w stored at 2*(w&3) + (w>>2)
__device__ __host__ __forceinline__ int lword(int p) { return (p >> 1) + 4 * (p & 1); }

#define ROWW 40                   // smem row stride in 32-bit words (rows hold 32 data words)
#define A_TILE_W (128 * ROWW)     // 5120
#define B_TILE_W (256 * ROWW)     // 10240
#define STAGE_W  (A_TILE_W + B_TILE_W)     // 15360 words
#define NSTAGE 3
#define SMEM_BYTES (NSTAGE * STAGE_W * 4)  // 184320

__device__ __forceinline__ float warpReduceSum(float v) {
#pragma unroll
    for (int o = 16; o > 0; o >>= 1) v += __shfl_xor_sync(0xffffffffu, v, o);
    return v;
}
__device__ __forceinline__ uint32_t smem_u32(const void* p) {
    uint32_t a;
    asm("{ .reg .u64 t; cvta.to.shared.u64 t, %1; cvt.u32.u64 %0, t; }" : "=r"(a) : "l"(p));
    return a;
}
__device__ __forceinline__ void cp16(uint32_t s, const void* g) {
    asm volatile("cp.async.cg.shared.global [%0], [%1], 16;" :: "r"(s), "l"(g));
}
#define CP_COMMIT() asm volatile("cp.async.commit_group;")
#define CP_WAIT1()  asm volatile("cp.async.wait_group 1;")
#define CP_WAIT0()  asm volatile("cp.async.wait_group 0;")

__device__ __forceinline__ void mma_f16(float* c, uint32_t a0, uint32_t a1, uint32_t a2,
                                        uint32_t a3, uint32_t b0, uint32_t b1) {
    asm volatile(
        "mma.sync.aligned.m16n8k16.row.col.f32.f16.f16.f32 "
        "{%0,%1,%2,%3}, {%4,%5,%6,%7}, {%8,%9}, {%0,%1,%2,%3};"
        : "+f"(c[0]), "+f"(c[1]), "+f"(c[2]), "+f"(c[3])
        : "r"(a0), "r"(a1), "r"(a2), "r"(a3), "r"(b0), "r"(b1));
}
__device__ __forceinline__ float hsum(uint32_t w) {
    __half2 h = *(__half2*)&w;
    float2 f = __half22float2(h);
    return f.x + f.y;
}

// ---------------- fused prep (rows) + transpose, one launch ----------------
// blocks [0,4096): L2-normalize 2 rows each -> g_xnh (word-permuted); zero g_rsum
// blocks [4096,8192): 32x32 transpose tile -> g_xth (permuted k columns)
__global__ void prep_trans_kernel(const float* __restrict__ x) {
    int b = blockIdx.x;
    int t = threadIdx.x;  // 256
    if (b < 4096) {
        __shared__ float sred[8];
        int row = 2 * b + (t >> 7);
        int tt = t & 127;
        if (tt == 0) g_rsum[row] = 0.f;
        float4 a = ((const float4*)(x + (size_t)row * D))[tt];
        float ss = a.x * a.x + a.y * a.y + a.z * a.z + a.w * a.w;
        ss = warpReduceSum(ss);
        if ((t & 31) == 0) sred[t >> 5] = ss;
        __syncthreads();
        int base = (t >> 7) * 4;
        float tot = sred[base] + sred[base + 1] + sred[base + 2] + sred[base + 3];
        float inv = 1.0f / fmaxf(sqrtf(tot), 1e-12f);
        float v[4] = {a.x * inv, a.y * inv, a.z * inv, a.w * inv};
        __half2* dst = (__half2*)(g_xnh + (size_t)row * D);
#pragma unroll
        for (int e = 0; e < 2; e++) {
            int w = 2 * tt + e;  // logical word
            int wg = w & 7;
            int sp = (w & ~7) | (2 * (wg & 3) + (wg >> 2));
            dst[sp] = __floats2half2_rn(v[2 * e], v[2 * e + 1]);
        }
    } else {
        __shared__ float tl[32][33];
        int id = b - 4096;
        int k0 = (id & 255) * 32, n0 = (id >> 8) * 32;
        int tx = t & 31, ty = t >> 5;  // 32 x 8
#pragma unroll
        for (int r = 0; r < 32; r += 8)
            tl[ty + r][tx] = x[(size_t)(k0 + ty + r) * D + n0 + tx];
        __syncthreads();
        int pw = (tx >> 1) & 7;
        int lh = (tx & ~15) | (2 * lword(pw) + (tx & 1));
#pragma unroll
        for (int r = 0; r < 32; r += 8)
            g_xth[(size_t)(n0 + ty + r) * NR + k0 + tx] = __float2half_rn(tl[lh][ty + r]);
    }
}

// ============== GEMM1: E = exp(xn @ xn^T - 1) fp16, 128x256 tiles, mirror + fused rowsum ==============
__global__ void __launch_bounds__(256, 1) gemm1_kernel() {
    // decode block: for each bj (0..31), bi in [0, min(64, 2bj+2))
    int kid = blockIdx.x, bj = 0;
    for (;;) {
        int cnum = min(64, 2 * bj + 2);
        if (kid < cnum) break;
        kid -= cnum; bj++;
    }
    int bi = kid;
    const int I0 = bi * 128, J0 = bj * 256;

    extern __shared__ uint32_t su[];
    uint32_t sbase = smem_u32(su);
    int t = threadIdx.x, wid = t >> 5, lane = t & 31;
    int g = lane >> 2, tq = lane & 3;
    int warpM = (wid >> 2) * 64, warpN = (wid & 3) * 64;

    const __half* aG = g_xnh + (size_t)(I0 + (t >> 1)) * D + (t & 1) * 32;
    const __half* bG = g_xnh + (size_t)(J0 + t) * D;
    uint32_t dstA = sbase + (uint32_t)((t >> 1) * ROWW + (t & 1) * 16) * 4;
    uint32_t dstB = sbase + (uint32_t)(A_TILE_W + t * ROWW) * 4;

    auto copy_stage = [&](int stage, int k0) {
        uint32_t off = (uint32_t)(stage * STAGE_W) * 4;
#pragma unroll
        for (int q = 0; q < 4; q++) cp16(dstA + off + q * 16, aG + k0 + q * 8);
#pragma unroll
        for (int q = 0; q < 8; q++) cp16(dstB + off + q * 16, bG + k0 + q * 8);
        CP_COMMIT();
    };

    float acc[4][8][4];
#pragma unroll
    for (int i = 0; i < 4; i++)
#pragma unroll
        for (int j = 0; j < 8; j++)
#pragma unroll
            for (int q = 0; q < 4; q++) acc[i][j][q] = 0.f;

    const int C = D / 64;  // 8 chunks
    copy_stage(0, 0);
    copy_stage(1, 64);

    int stage = 0;
    for (int c = 0; c < C; c++) {
        if (c + 2 < C) CP_WAIT1(); else CP_WAIT0();
        __syncthreads();
        if (c + 2 < C) {
            int ns = stage + 2; if (ns >= NSTAGE) ns -= NSTAGE;
            copy_stage(ns, (c + 2) * 64);
        }
        const uint32_t* sA = su + stage * STAGE_W;
        const uint32_t* sB = sA + A_TILE_W;
#pragma unroll
        for (int s = 0; s < 4; s++) {  // 4 k16 steps per 64-half chunk
            uint32_t af[4][4], bf[8][2];
#pragma unroll
            for (int i = 0; i < 4; i++) {
                const uint32_t* pa = sA + (warpM + i * 16 + g) * ROWW + 8 * s + 2 * tq;
                uint2 lo = *(const uint2*)pa;              // (a0, a2)
                uint2 hi = *(const uint2*)(pa + 8 * ROWW); // (a1, a3)
                af[i][0] = lo.x; af[i][1] = hi.x; af[i][2] = lo.y; af[i][3] = hi.y;
            }
#pragma unroll
            for (int j = 0; j < 8; j++) {
                uint2 b = *(const uint2*)(sB + (warpN + j * 8 + g) * ROWW + 8 * s + 2 * tq);
                bf[j][0] = b.x; bf[j][1] = b.y;
            }
#pragma unroll
            for (int i = 0; i < 4; i++)
#pragma unroll
                for (int j = 0; j < 8; j++)
                    mma_f16(acc[i][j], af[i][0], af[i][1], af[i][2], af[i][3],
                            bf[j][0], bf[j][1]);
        }
        if (++stage >= NSTAGE) stage = 0;
    }
    __syncthreads();

    // ---- epilogue: exp(s-1) -> eb_w[128][131] half2 words -> permuted fp16 writes ----
    const int EBW = 131;
    uint32_t* eb = su;
#pragma unroll
    for (int i = 0; i < 4; i++)
#pragma unroll
        for (int j = 0; j < 8; j++) {
            int r0 = warpM + i * 16 + g;
            int wrd = ((warpN + j * 8) >> 1) + tq;
            __half2 lo = __floats2half2_rn(__expf(acc[i][j][0] - 1.0f), __expf(acc[i][j][1] - 1.0f));
            __half2 hi = __floats2half2_rn(__expf(acc[i][j][2] - 1.0f), __expf(acc[i][j][3] - 1.0f));
            eb[r0 * EBW + wrd]       = *(uint32_t*)&lo;
            eb[(r0 + 8) * EBW + wrd] = *(uint32_t*)&hi;
        }
    __syncthreads();

    // natural: rows I0+r, stored cols J0..: always contribute 256-col partial row sums
    {
        int b = 8 * (lane >> 1) + 2 * (lane & 1);
#pragma unroll 1
        for (int it = 0; it < 16; it++) {
            int r = wid * 16 + it;
            const uint32_t* src = eb + r * EBW;
            uint4 v = make_uint4(src[b], src[b + 4], src[b + 1], src[b + 5]);
            *(uint4*)(g_Eh + (size_t)(I0 + r) * NR + J0 + 8 * lane) = v;
            float fs = hsum(v.x) + hsum(v.y) + hsum(v.z) + hsum(v.w);
            fs = warpReduceSum(fs);
            if (lane == 0) atomicAdd(&g_rsum[I0 + r], fs);
        }
    }
    // mirror: rows J0+cc, stored cols I0..: contribute only when not naturally covered
    {
        bool addMirror = (bi < 2 * bj);
        int w = 8 * (lane >> 2) + (lane & 3);
        int r0 = 2 * w;
#pragma unroll 1
        for (int it = 0; it < 32; it++) {
            int cc = wid * 32 + it;
            int cw = cc >> 1, ch = (cc & 1) * 16;
            uint32_t h0 = (eb[(r0)     * EBW + cw] >> ch) & 0xffffu;
            uint32_t h1 = (eb[(r0 + 1) * EBW + cw] >> ch) & 0xffffu;
            uint32_t h2 = (eb[(r0 + 8) * EBW + cw] >> ch) & 0xffffu;
            uint32_t h3 = (eb[(r0 + 9) * EBW + cw] >> ch) & 0xffffu;
            uint2 v = make_uint2(h0 | (h1 << 16), h2 | (h3 << 16));
            *(uint2*)(g_Eh + (size_t)(J0 + cc) * NR + I0 + 4 * lane) = v;
            if (addMirror) {
                float fs = hsum(v.x) + hsum(v.y);
                fs = warpReduceSum(fs);
                if (lane == 0) atomicAdd(&g_rsum[J0 + cc], fs);
            }
        }
    }
}

// ---------------- invr: 1/rsum -> natural + permuted ----------------
__global__ void invr_kernel() {
    int i = blockIdx.x * 256 + threadIdx.x;
    float inv = 1.0f / g_rsum[i];
    g_invr[i] = inv;
    int w = (i >> 1) & 7, e2 = i & 1;
    int sp = (i & ~15) | (2 * (2 * (w & 3) + (w >> 2)) + e2);
    g_invr_p[sp] = inv;
}

// ============== GEMM2: xneg = [E*(invr_i+invr_k)] @ x, 128x256 tiles ==============
__global__ void __launch_bounds__(256, 1) gemm2_kernel() {
    const int n0 = blockIdx.x * 256;  // 0..1
    const int I0 = blockIdx.y * 128;  // 0..63

    extern __shared__ uint32_t su[];
    uint32_t sbase = smem_u32(su);
    int t = threadIdx.x, wid = t >> 5, lane = t & 31;
    int g = lane >> 2, tq = lane & 3;
    int warpM = (wid >> 2) * 64, warpN = (wid & 3) * 64;

    const float ri = g_invr[I0 + (t >> 1)];
    const __half* aG = g_Eh + (size_t)(I0 + (t >> 1)) * NR + (t & 1) * 32;
    const __half* bG = g_xth + (size_t)(n0 + t) * NR;
    uint32_t stsA = sbase + (uint32_t)((t >> 1) * ROWW + (t & 1) * 16) * 4;
    uint32_t dstB = sbase + (uint32_t)(A_TILE_W + t * ROWW) * 4;

    uint4 pa[4];
    auto ldgA = [&](int k0) {
#pragma unroll
        for (int q = 0; q < 4; q++) pa[q] = ((const uint4*)(aG + k0))[q];
    };
    auto stsA_f = [&](int stg, int k0) {
        const float* rp = g_invr_p + k0 + (t & 1) * 32;
        uint32_t dst = stsA + (uint32_t)(stg * STAGE_W) * 4;
#pragma unroll
        for (int q = 0; q < 4; q++) {
            float4 r0 = __ldg((const float4*)(rp + q * 8));
            float4 r1 = __ldg((const float4*)(rp + q * 8 + 4));
            const __half2* hp = (const __half2*)&pa[q];
            float2 f0 = __half22float2(hp[0]);
            float2 f1 = __half22float2(hp[1]);
            float2 f2 = __half22float2(hp[2]);
            float2 f3 = __half22float2(hp[3]);
            __half2 o0 = __floats2half2_rn(f0.x * (ri + r0.x), f0.y * (ri + r0.y));
            __half2 o1 = __floats2half2_rn(f1.x * (ri + r0.z), f1.y * (ri + r0.w));
            __half2 o2 = __floats2half2_rn(f2.x * (ri + r1.x), f2.y * (ri + r1.y));
            __half2 o3 = __floats2half2_rn(f3.x * (ri + r1.z), f3.y * (ri + r1.w));
            asm volatile("st.shared.v4.b32 [%0], {%1,%2,%3,%4};"
                         :: "r"(dst + q * 16), "r"(*(uint32_t*)&o0), "r"(*(uint32_t*)&o1),
                            "r"(*(uint32_t*)&o2), "r"(*(uint32_t*)&o3));
        }
    };
    auto cpB = [&](int stg, int k0) {
        uint32_t off = (uint32_t)(stg * STAGE_W) * 4;
#pragma unroll
        for (int q = 0; q < 8; q++) cp16(dstB + off + q * 16, bG + k0 + q * 8);
        CP_COMMIT();
    };

    float acc[4][8][4];
#pragma unroll
    for (int i = 0; i < 4; i++)
#pragma unroll
        for (int j = 0; j < 8; j++)
#pragma unroll
            for (int q = 0; q < 4; q++) acc[i][j][q] = 0.f;

    const int C = NR / 64;  // 128 chunks
    ldgA(0); stsA_f(0, 0); cpB(0, 0);
    ldgA(64); stsA_f(1, 64); cpB(1, 64);
    ldgA(128);

    int stage = 0;
    for (int c = 0; c < C; c++) {
        if (c + 2 < C) CP_WAIT1(); else CP_WAIT0();
        __syncthreads();
        if (c + 2 < C) {
            int ns = stage + 2; if (ns >= NSTAGE) ns -= NSTAGE;
            stsA_f(ns, (c + 2) * 64);   // consumes pa (chunk c+2)
            cpB(ns, (c + 2) * 64);
            if (c + 3 < C) ldgA((c + 3) * 64);
        }
        const uint32_t* sA = su + stage * STAGE_W;
        const uint32_t* sB = sA + A_TILE_W;
#pragma unroll
        for (int s = 0; s < 4; s++) {
            uint32_t af[4][4], bf[8][2];
#pragma unroll
            for (int i = 0; i < 4; i++) {
                const uint32_t* p = sA + (warpM + i * 16 + g) * ROWW + 8 * s + 2 * tq;
                uint2 lo = *(const uint2*)p;
                uint2 hi = *(const uint2*)(p + 8 * ROWW);
                af[i][0] = lo.x; af[i][1] = hi.x; af[i][2] = lo.y; af[i][3] = hi.y;
            }
#pragma unroll
            for (int j = 0; j < 8; j++) {
                uint2 b = *(const uint2*)(sB + (warpN + j * 8 + g) * ROWW + 8 * s + 2 * tq);
                bf[j][0] = b.x; bf[j][1] = b.y;
            }
#pragma unroll
            for (int i = 0; i < 4; i++)
#pragma unroll
                for (int j = 0; j < 8; j++)
                    mma_f16(acc[i][j], af[i][0], af[i][1], af[i][2], af[i][3],
                            bf[j][0], bf[j][1]);
        }
        if (++stage >= NSTAGE) stage = 0;
    }

    // epilogue: f32 stores, n not permuted
#pragma unroll
    for (int i = 0; i < 4; i++)
#pragma unroll
        for (int j = 0; j < 8; j++) {
            int r0 = I0 + warpM + i * 16 + g;
            int c0 = n0 + warpN + j * 8 + 2 * tq;
            *(float2*)(g_xneg + (size_t)r0 * D + c0)       = make_float2(acc[i][j][0], acc[i][j][1]);
            *(float2*)(g_xneg + (size_t)(r0 + 8) * D + c0) = make_float2(acc[i][j][2], acc[i][j][3]);
        }
}

// ---------------- y = x - SCALE*xneg, LayerNorm ----------------
__global__ void ln_kernel(const float* __restrict__ x, const float* __restrict__ gamma,
                          const float* __restrict__ beta, float* __restrict__ out) {
    __shared__ float s1[4], s2[4];
    int row = blockIdx.x, t = threadIdx.x;  // 128 threads
    float4 xv = ((const float4*)(x + (size_t)row * D))[t];
    float4 nv = ((const float4*)(g_xneg + (size_t)row * D))[t];
    float4 y = make_float4(xv.x - SCALEF * nv.x, xv.y - SCALEF * nv.y,
                           xv.z - SCALEF * nv.z, xv.w - SCALEF * nv.w);
    float s = y.x + y.y + y.z + y.w;
    float q = y.x * y.x + y.y * y.y + y.z * y.z + y.w * y.w;
    s = warpReduceSum(s);
    q = warpReduceSum(q);
    if ((t & 31) == 0) { s1[t >> 5] = s; s2[t >> 5] = q; }
    __syncthreads();
    float sum = s1[0] + s1[1] + s1[2] + s1[3];
    float sq  = s2[0] + s2[1] + s2[2] + s2[3];
    float mean = sum * (1.0f / D);
    float var = sq * (1.0f / D) - mean * mean;
    float rstd = rsqrtf(var + 1e-6f);
    float4 gm = ((const float4*)gamma)[t];
    float4 b = ((const float4*)beta)[t];
    float4 o;
    o.x = (y.x - mean) * rstd * gm.x + b.x;
    o.y = (y.y - mean) * rstd * gm.y + b.y;
    o.z = (y.z - mean) * rstd * gm.z + b.z;
    o.w = (y.w - mean) * rstd * gm.w + b.w;
    ((float4*)out)[(size_t)row * (D / 4) + t] = o;
}

extern "C" void kernel_launch(void* const* d_in, const int* in_sizes, int n_in,
                              void* d_out, int out_size) {
    const float* x     = (const float*)d_in[0];
    const float* gamma = (const float*)d_in[1];
    const float* beta  = (const float*)d_in[2];
    float* out = (float*)d_out;

    cudaFuncSetAttribute(gemm1_kernel, cudaFuncAttributeMaxDynamicSharedMemorySize, SMEM_BYTES);
    cudaFuncSetAttribute(gemm2_kernel, cudaFuncAttributeMaxDynamicSharedMemorySize, SMEM_BYTES);

    prep_trans_kernel<<<8192, 256>>>(x);
    gemm1_kernel<<<1056, 256, SMEM_BYTES>>>();
    invr_kernel<<<NR / 256, 256>>>();
    gemm2_kernel<<<dim3(2, 64), 256, SMEM_BYTES>>>();
    ln_kernel<<<NR, 128>>>(x, gamma, beta, out);
}

// round 14
// speedup vs baseline: 1.1969x; 1.0245x over previous
#include <cuda_runtime.h>
#include <cuda_fp16.h>
#include <math.h>
#include <stdint.h>

#define NR 8192
#define D  512
#define SCALEF 0.1f

__device__ __half g_Eh[(size_t)NR * NR];     // 128 MB: E fp16, k-word-permuted columns
__device__ __half g_xnh[(size_t)NR * D];     // normalized x fp16, permuted features
__device__ __half g_xth[(size_t)D * NR];     // x^T fp16 [512][8192], permuted columns
__device__ float  g_xneg[(size_t)NR * D];
__device__ float  g_rsum[NR];                // row sums (atomic accum in gemm1 epilogue)
__device__ float  g_invr[NR];                // natural order
__device__ float  g_invr_p[NR];              // stored(half)-position order

// word-level perm within 8-word (16-half) groups: stored word p holds logical word
// l(p) = (p>>1) + 4*(p&1); inverse: logical w stored at 2*(w&3) + (w>>2)
__device__ __host__ __forceinline__ int lword(int p) { return (p >> 1) + 4 * (p & 1); }

#define ROWW 40                   // smem row stride in 32-bit words (rows hold 32 data words)
#define A_TILE_W (128 * ROWW)     // 5120
#define B_TILE_W (128 * ROWW)     // 5120 (128-wide tiles now)
#define STAGE_W  (A_TILE_W + B_TILE_W)   // 10240 words = 40KB
#define SMEM_BYTES (2 * STAGE_W * 4)     // 81920 -> 2 CTAs/SM

__device__ __forceinline__ float warpReduceSum(float v) {
#pragma unroll
    for (int o = 16; o > 0; o >>= 1) v += __shfl_xor_sync(0xffffffffu, v, o);
    return v;
}
__device__ __forceinline__ uint32_t smem_u32(const void* p) {
    uint32_t a;
    asm("{ .reg .u64 t; cvta.to.shared.u64 t, %1; cvt.u32.u64 %0, t; }" : "=r"(a) : "l"(p));
    return a;
}
__device__ __forceinline__ void cp16(uint32_t s, const void* g) {
    asm volatile("cp.async.cg.shared.global [%0], [%1], 16;" :: "r"(s), "l"(g));
}
#define CP_COMMIT() asm volatile("cp.async.commit_group;")
#define CP_WAIT1()  asm volatile("cp.async.wait_group 1;")
#define CP_WAIT0()  asm volatile("cp.async.wait_group 0;")

__device__ __forceinline__ void mma_f16(float* c, uint32_t a0, uint32_t a1, uint32_t a2,
                                        uint32_t a3, uint32_t b0, uint32_t b1) {
    asm volatile(
        "mma.sync.aligned.m16n8k16.row.col.f32.f16.f16.f32 "
        "{%0,%1,%2,%3}, {%4,%5,%6,%7}, {%8,%9}, {%0,%1,%2,%3};"
        : "+f"(c[0]), "+f"(c[1]), "+f"(c[2]), "+f"(c[3])
        : "r"(a0), "r"(a1), "r"(a2), "r"(a3), "r"(b0), "r"(b1));
}
__device__ __forceinline__ float hsum(uint32_t w) {
    __half2 h = *(__half2*)&w;
    float2 f = __half22float2(h);
    return f.x + f.y;
}

// ---------------- fused prep (rows) + transpose, one launch ----------------
__global__ void prep_trans_kernel(const float* __restrict__ x) {
    int b = blockIdx.x;
    int t = threadIdx.x;  // 256
    if (b < 4096) {
        __shared__ float sred[8];
        int row = 2 * b + (t >> 7);
        int tt = t & 127;
        if (tt == 0) g_rsum[row] = 0.f;
        float4 a = ((const float4*)(x + (size_t)row * D))[tt];
        float ss = a.x * a.x + a.y * a.y + a.z * a.z + a.w * a.w;
        ss = warpReduceSum(ss);
        if ((t & 31) == 0) sred[t >> 5] = ss;
        __syncthreads();
        int base = (t >> 7) * 4;
        float tot = sred[base] + sred[base + 1] + sred[base + 2] + sred[base + 3];
        float inv = 1.0f / fmaxf(sqrtf(tot), 1e-12f);
        float v[4] = {a.x * inv, a.y * inv, a.z * inv, a.w * inv};
        __half2* dst = (__half2*)(g_xnh + (size_t)row * D);
#pragma unroll
        for (int e = 0; e < 2; e++) {
            int w = 2 * tt + e;  // logical word
            int wg = w & 7;
            int sp = (w & ~7) | (2 * (wg & 3) + (wg >> 2));
            dst[sp] = __floats2half2_rn(v[2 * e], v[2 * e + 1]);
        }
    } else {
        __shared__ float tl[32][33];
        int id = b - 4096;
        int k0 = (id & 255) * 32, n0 = (id >> 8) * 32;
        int tx = t & 31, ty = t >> 5;  // 32 x 8
#pragma unroll
        for (int r = 0; r < 32; r += 8)
            tl[ty + r][tx] = x[(size_t)(k0 + ty + r) * D + n0 + tx];
        __syncthreads();
        int pw = (tx >> 1) & 7;
        int lh = (tx & ~15) | (2 * lword(pw) + (tx & 1));
#pragma unroll
        for (int r = 0; r < 32; r += 8)
            g_xth[(size_t)(n0 + ty + r) * NR + k0 + tx] = __float2half_rn(tl[lh][ty + r]);
    }
}

// ============== GEMM1: E = exp(xn @ xn^T - 1) fp16, 128x128 tiles, triangular + mirror + rowsum ==============
__global__ void __launch_bounds__(256, 2) gemm1_kernel() {
    // triangular decode: bi <= bj, 2080 blocks
    int kid = blockIdx.x;
    int bj = (int)((sqrtf(8.0f * (float)kid + 1.0f) - 1.0f) * 0.5f);
    while ((bj + 1) * (bj + 2) / 2 <= kid) bj++;
    while (bj * (bj + 1) / 2 > kid) bj--;
    int bi = kid - bj * (bj + 1) / 2;
    const int I0 = bi * 128, J0 = bj * 128;

    extern __shared__ uint32_t su[];
    uint32_t sbase = smem_u32(su);
    int t = threadIdx.x, wid = t >> 5, lane = t & 31;
    int g = lane >> 2, tq = lane & 3;
    int warpM = (wid >> 2) * 64, warpN = (wid & 3) * 32;

    const __half* aG = g_xnh + (size_t)(I0 + (t >> 1)) * D + (t & 1) * 32;
    const __half* bG = g_xnh + (size_t)(J0 + (t >> 1)) * D + (t & 1) * 32;
    uint32_t dstA = sbase + (uint32_t)((t >> 1) * ROWW + (t & 1) * 16) * 4;
    uint32_t dstB = sbase + (uint32_t)(A_TILE_W + (t >> 1) * ROWW + (t & 1) * 16) * 4;

    auto copy_stage = [&](int stage, int k0) {
        uint32_t off = (uint32_t)(stage * STAGE_W) * 4;
#pragma unroll
        for (int q = 0; q < 4; q++) {
            cp16(dstA + off + q * 16, aG + k0 + q * 8);
            cp16(dstB + off + q * 16, bG + k0 + q * 8);
        }
        CP_COMMIT();
    };

    float acc[4][4][4];
#pragma unroll
    for (int i = 0; i < 4; i++)
#pragma unroll
        for (int j = 0; j < 4; j++)
#pragma unroll
            for (int q = 0; q < 4; q++) acc[i][j][q] = 0.f;

    const int C = D / 64;  // 8 chunks
    copy_stage(0, 0);
    copy_stage(1, 64);

    for (int c = 0; c < C; c++) {
        if (c + 2 < C) CP_WAIT1(); else CP_WAIT0();
        __syncthreads();
        const uint32_t* sA = su + (c & 1) * STAGE_W;
        const uint32_t* sB = sA + A_TILE_W;
#pragma unroll
        for (int s = 0; s < 4; s++) {  // 4 k16 steps per 64-half chunk
            uint32_t af[4][4], bf[4][2];
#pragma unroll
            for (int i = 0; i < 4; i++) {
                const uint32_t* pa = sA + (warpM + i * 16 + g) * ROWW + 8 * s + 2 * tq;
                uint2 lo = *(const uint2*)pa;              // (a0, a2)
                uint2 hi = *(const uint2*)(pa + 8 * ROWW); // (a1, a3)
                af[i][0] = lo.x; af[i][1] = hi.x; af[i][2] = lo.y; af[i][3] = hi.y;
            }
#pragma unroll
            for (int j = 0; j < 4; j++) {
                uint2 b = *(const uint2*)(sB + (warpN + j * 8 + g) * ROWW + 8 * s + 2 * tq);
                bf[j][0] = b.x; bf[j][1] = b.y;
            }
#pragma unroll
            for (int i = 0; i < 4; i++)
#pragma unroll
                for (int j = 0; j < 4; j++)
                    mma_f16(acc[i][j], af[i][0], af[i][1], af[i][2], af[i][3],
                            bf[j][0], bf[j][1]);
        }
        __syncthreads();
        if (c + 2 < C) copy_stage(c & 1, (c + 2) * 64);
    }
    __syncthreads();

    // ---- epilogue: exp(s-1) -> eb_w[128][67] half2 words -> permuted fp16 writes + rowsums ----
    const int EBW = 67;
    uint32_t* eb = su;
#pragma unroll
    for (int i = 0; i < 4; i++)
#pragma unroll
        for (int j = 0; j < 4; j++) {
            int r0 = warpM + i * 16 + g;
            int wrd = ((warpN + j * 8) >> 1) + tq;
            __half2 lo = __floats2half2_rn(__expf(acc[i][j][0] - 1.0f), __expf(acc[i][j][1] - 1.0f));
            __half2 hi = __floats2half2_rn(__expf(acc[i][j][2] - 1.0f), __expf(acc[i][j][3] - 1.0f));
            eb[r0 * EBW + wrd]       = *(uint32_t*)&lo;
            eb[(r0 + 8) * EBW + wrd] = *(uint32_t*)&hi;
        }
    __syncthreads();

    // natural: rows I0+r, stored cols J0..: warp wid covers rows wid*16..+15; rowsum always
    {
        int s0 = (lane >> 2) * 8 + (lane & 3);  // logical source word for stored word 2*lane
#pragma unroll 1
        for (int it = 0; it < 16; it++) {
            int r = wid * 16 + it;
            const uint32_t* src = eb + r * EBW;
            uint2 v = make_uint2(src[s0], src[s0 + 4]);
            *(uint2*)(g_Eh + (size_t)(I0 + r) * NR + J0 + 4 * lane) = v;
            float fs = hsum(v.x) + hsum(v.y);
            fs = warpReduceSum(fs);
            if (lane == 0) atomicAdd(&g_rsum[I0 + r], fs);
        }
    }
    // mirror: rows J0+cc, stored cols I0..: warp covers rows wid*16..+15; rowsum iff off-diagonal
    {
        bool addMirror = (bi != bj);
        int w = 8 * (lane >> 2) + (lane & 3);
        int r0 = 2 * w;
#pragma unroll 1
        for (int it = 0; it < 16; it++) {
            int cc = wid * 16 + it;
            int cw = cc >> 1, ch = (cc & 1) * 16;
            uint32_t h0 = (eb[(r0)     * EBW + cw] >> ch) & 0xffffu;
            uint32_t h1 = (eb[(r0 + 1) * EBW + cw] >> ch) & 0xffffu;
            uint32_t h2 = (eb[(r0 + 8) * EBW + cw] >> ch) & 0xffffu;
            uint32_t h3 = (eb[(r0 + 9) * EBW + cw] >> ch) & 0xffffu;
            uint2 v = make_uint2(h0 | (h1 << 16), h2 | (h3 << 16));
            *(uint2*)(g_Eh + (size_t)(J0 + cc) * NR + I0 + 4 * lane) = v;
            if (addMirror) {
                float fs = hsum(v.x) + hsum(v.y);
                fs = warpReduceSum(fs);
                if (lane == 0) atomicAdd(&g_rsum[J0 + cc], fs);
            }
        }
    }
}

// ---------------- invr: 1/rsum -> natural + permuted ----------------
__global__ void invr_kernel() {
    int i = blockIdx.x * 256 + threadIdx.x;
    float inv = 1.0f / g_rsum[i];
    g_invr[i] = inv;
    int w = (i >> 1) & 7, e2 = i & 1;
    int sp = (i & ~15) | (2 * (2 * (w & 3) + (w >> 2)) + e2);
    g_invr_p[sp] = inv;
}

// ============== GEMM2: xneg = [E*(invr_i+invr_k)] @ x, 128x128 tiles, 2 CTA/SM ==============
__global__ void __launch_bounds__(256, 2) gemm2_kernel() {
    const int n0 = blockIdx.x * 128;  // 0..3
    const int I0 = blockIdx.y * 128;  // 0..63

    extern __shared__ uint32_t su[];
    uint32_t sbase = smem_u32(su);
    int t = threadIdx.x, wid = t >> 5, lane = t & 31;
    int g = lane >> 2, tq = lane & 3;
    int warpM = (wid >> 2) * 64, warpN = (wid & 3) * 32;

    const float ri = g_invr[I0 + (t >> 1)];
    const __half* aG = g_Eh + (size_t)(I0 + (t >> 1)) * NR + (t & 1) * 32;
    const __half* bG = g_xth + (size_t)(n0 + (t >> 1)) * NR + (t & 1) * 32;
    uint32_t stsA = sbase + (uint32_t)((t >> 1) * ROWW + (t & 1) * 16) * 4;
    uint32_t dstB = sbase + (uint32_t)(A_TILE_W + (t >> 1) * ROWW + (t & 1) * 16) * 4;

    uint4 pa[4];
    auto ldgA = [&](int k0) {
#pragma unroll
        for (int q = 0; q < 4; q++) pa[q] = ((const uint4*)(aG + k0))[q];
    };
    auto stsA_f = [&](int stg, int k0) {
        const float* rp = g_invr_p + k0 + (t & 1) * 32;
        uint32_t dst = stsA + (uint32_t)(stg * STAGE_W) * 4;
#pragma unroll
        for (int q = 0; q < 4; q++) {
            float4 r0 = __ldg((const float4*)(rp + q * 8));
            float4 r1 = __ldg((const float4*)(rp + q * 8 + 4));
            const __half2* hp = (const __half2*)&pa[q];
            float2 f0 = __half22float2(hp[0]);
            float2 f1 = __half22float2(hp[1]);
            float2 f2 = __half22float2(hp[2]);
            float2 f3 = __half22float2(hp[3]);
            __half2 o0 = __floats2half2_rn(f0.x * (ri + r0.x), f0.y * (ri + r0.y));
            __half2 o1 = __floats2half2_rn(f1.x * (ri + r0.z), f1.y * (ri + r0.w));
            __half2 o2 = __floats2half2_rn(f2.x * (ri + r1.x), f2.y * (ri + r1.y));
            __half2 o3 = __floats2half2_rn(f3.x * (ri + r1.z), f3.y * (ri + r1.w));
            asm volatile("st.shared.v4.b32 [%0], {%1,%2,%3,%4};"
                         :: "r"(dst + q * 16), "r"(*(uint32_t*)&o0), "r"(*(uint32_t*)&o1),
                            "r"(*(uint32_t*)&o2), "r"(*(uint32_t*)&o3));
        }
    };
    auto cpB = [&](int stg, int k0) {
        uint32_t off = (uint32_t)(stg * STAGE_W) * 4;
#pragma unroll
        for (int q = 0; q < 4; q++) cp16(dstB + off + q * 16, bG + k0 + q * 8);
        CP_COMMIT();
    };

    float acc[4][4][4];
#pragma unroll
    for (int i = 0; i < 4; i++)
#pragma unroll
        for (int j = 0; j < 4; j++)
#pragma unroll
            for (int q = 0; q < 4; q++) acc[i][j][q] = 0.f;

    const int C = NR / 64;  // 128 chunks
    ldgA(0); stsA_f(0, 0); cpB(0, 0);
    ldgA(64); stsA_f(1, 64); cpB(1, 64);
    ldgA(128);

    for (int c = 0; c < C; c++) {
        if (c + 2 < C) CP_WAIT1(); else CP_WAIT0();
        __syncthreads();
        const uint32_t* sA = su + (c & 1) * STAGE_W;
        const uint32_t* sB = sA + A_TILE_W;
#pragma unroll
        for (int s = 0; s < 4; s++) {
            uint32_t af[4][4], bf[4][2];
#pragma unroll
            for (int i = 0; i < 4; i++) {
                const uint32_t* p = sA + (warpM + i * 16 + g) * ROWW + 8 * s + 2 * tq;
                uint2 lo = *(const uint2*)p;
                uint2 hi = *(const uint2*)(p + 8 * ROWW);
                af[i][0] = lo.x; af[i][1] = hi.x; af[i][2] = lo.y; af[i][3] = hi.y;
            }
#pragma unroll
            for (int j = 0; j < 4; j++) {
                uint2 b = *(const uint2*)(sB + (warpN + j * 8 + g) * ROWW + 8 * s + 2 * tq);
                bf[j][0] = b.x; bf[j][1] = b.y;
            }
#pragma unroll
            for (int i = 0; i < 4; i++)
#pragma unroll
                for (int j = 0; j < 4; j++)
                    mma_f16(acc[i][j], af[i][0], af[i][1], af[i][2], af[i][3],
                            bf[j][0], bf[j][1]);
        }
        __syncthreads();
        if (c + 2 < C) {
            stsA_f(c & 1, (c + 2) * 64);   // consumes pa (chunk c+2)
            cpB(c & 1, (c + 2) * 64);
            if (c + 3 < C) ldgA((c + 3) * 64);
        }
    }

    // epilogue: f32 stores, n not permuted
#pragma unroll
    for (int i = 0; i < 4; i++)
#pragma unroll
        for (int j = 0; j < 4; j++) {
            int r0 = I0 + warpM + i * 16 + g;
            int c0 = n0 + warpN + j * 8 + 2 * tq;
            *(float2*)(g_xneg + (size_t)r0 * D + c0)       = make_float2(acc[i][j][0], acc[i][j][1]);
            *(float2*)(g_xneg + (size_t)(r0 + 8) * D + c0) = make_float2(acc[i][j][2], acc[i][j][3]);
        }
}

// ---------------- y = x - SCALE*xneg, LayerNorm ----------------
__global__ void ln_kernel(const float* __restrict__ x, const float* __restrict__ gamma,
                          const float* __restrict__ beta, float* __restrict__ out) {
    __shared__ float s1[4], s2[4];
    int row = blockIdx.x, t = threadIdx.x;  // 128 threads
    float4 xv = ((const float4*)(x + (size_t)row * D))[t];
    float4 nv = ((const float4*)(g_xneg + (size_t)row * D))[t];
    float4 y = make_float4(xv.x - SCALEF * nv.x, xv.y - SCALEF * nv.y,
                           xv.z - SCALEF * nv.z, xv.w - SCALEF * nv.w);
    float s = y.x + y.y + y.z + y.w;
    float q = y.x * y.x + y.y * y.y + y.z * y.z + y.w * y.w;
    s = warpReduceSum(s);
    q = warpReduceSum(q);
    if ((t & 31) == 0) { s1[t >> 5] = s; s2[t >> 5] = q; }
    __syncthreads();
    float sum = s1[0] + s1[1] + s1[2] + s1[3];
    float sq  = s2[0] + s2[1] + s2[2] + s2[3];
    float mean = sum * (1.0f / D);
    float var = sq * (1.0f / D) - mean * mean;
    float rstd = rsqrtf(var + 1e-6f);
    float4 gm = ((const float4*)gamma)[t];
    float4 b = ((const float4*)beta)[t];
    float4 o;
    o.x = (y.x - mean) * rstd * gm.x + b.x;
    o.y = (y.y - mean) * rstd * gm.y + b.y;
    o.z = (y.z - mean) * rstd * gm.z + b.z;
    o.w = (y.w - mean) * rstd * gm.w + b.w;
    ((float4*)out)[(size_t)row * (D / 4) + t] = o;
}

extern "C" void kernel_launch(void* const* d_in, const int* in_sizes, int n_in,
                              void* d_out, int out_size) {
    const float* x     = (const float*)d_in[0];
    const float* gamma = (const float*)d_in[1];
    const float* beta  = (const float*)d_in[2];
    float* out = (float*)d_out;

    cudaFuncSetAttribute(gemm1_kernel, cudaFuncAttributeMaxDynamicSharedMemorySize, SMEM_BYTES);
    cudaFuncSetAttribute(gemm2_kernel, cudaFuncAttributeMaxDynamicSharedMemorySize, SMEM_BYTES);

    prep_trans_kernel<<<8192, 256>>>(x);
    gemm1_kernel<<<64 * 65 / 2, 256, SMEM_BYTES>>>();
    invr_kernel<<<NR / 256, 256>>>();
    gemm2_kernel<<<dim3(4, 64), 256, SMEM_BYTES>>>();
    ln_kernel<<<NR, 128>>>(x, gamma, beta, out);
}

// round 16
// speedup vs baseline: 1.2900x; 1.0778x over previous
#include <cuda_runtime.h>
#include <cuda_fp16.h>
#include <math.h>
#include <stdint.h>

#define NR 8192
#define D  512
#define SCALEF 0.1f
#define A8SCALE 4096.0f

__device__ __half   g_Eh[(size_t)NR * NR];   // 128 MB: E fp16, k-word-permuted columns
__device__ uint8_t  g_A8[(size_t)NR * NR];   // 64 MB: e4m3 of E*(invr_i+invr_j)*4096, byte-permuted
__device__ __half   g_xnh[(size_t)NR * D];   // normalized x fp16, permuted features
__device__ uint8_t  g_xt8[(size_t)D * NR];   // x^T e4m3 [512][8192], byte-permuted columns
__device__ float    g_xneg[(size_t)NR * D];
__device__ float    g_rsum[NR];
__device__ float    g_invr[NR];              // natural order

// word perm within groups: stored word p holds logical word l(p) = (p>>1) + 4*(p&1)
__device__ __host__ __forceinline__ int lword(int p) { return (p >> 1) + 4 * (p & 1); }

// ---- gemm1 (fp16) smem config: 128x128 tiles, 2-stage, 2 CTA/SM ----
#define ROWW 40
#define A_TILE_W (128 * ROWW)
#define B_TILE_W (128 * ROWW)
#define STAGE_W  (A_TILE_W + B_TILE_W)
#define SMEM_BYTES (2 * STAGE_W * 4)     // 81920

// ---- gemm2 (fp8) smem config: 128x256 tiles, 3-stage ----
#define F8_ROWW 24                        // 16 data words + 8 pad (conflict-free LDS.64 phases)
#define F8_A_W (128 * F8_ROWW)            // 3072
#define F8_B_W (256 * F8_ROWW)            // 6144
#define F8_STAGE_W (F8_A_W + F8_B_W)      // 9216 words = 36 KB
#define F8_SMEM (3 * F8_STAGE_W * 4)      // 110592

__device__ __forceinline__ float warpReduceSum(float v) {
#pragma unroll
    for (int o = 16; o > 0; o >>= 1) v += __shfl_xor_sync(0xffffffffu, v, o);
    return v;
}
__device__ __forceinline__ uint32_t smem_u32(const void* p) {
    uint32_t a;
    asm("{ .reg .u64 t; cvta.to.shared.u64 t, %1; cvt.u32.u64 %0, t; }" : "=r"(a) : "l"(p));
    return a;
}
__device__ __forceinline__ void cp16(uint32_t s, const void* g) {
    asm volatile("cp.async.cg.shared.global [%0], [%1], 16;" :: "r"(s), "l"(g));
}
#define CP_COMMIT() asm volatile("cp.async.commit_group;")
#define CP_WAIT1()  asm volatile("cp.async.wait_group 1;")
#define CP_WAIT0()  asm volatile("cp.async.wait_group 0;")

__device__ __forceinline__ void mma_f16(float* c, uint32_t a0, uint32_t a1, uint32_t a2,
                                        uint32_t a3, uint32_t b0, uint32_t b1) {
    asm volatile(
        "mma.sync.aligned.m16n8k16.row.col.f32.f16.f16.f32 "
        "{%0,%1,%2,%3}, {%4,%5,%6,%7}, {%8,%9}, {%0,%1,%2,%3};"
        : "+f"(c[0]), "+f"(c[1]), "+f"(c[2]), "+f"(c[3])
        : "r"(a0), "r"(a1), "r"(a2), "r"(a3), "r"(b0), "r"(b1));
}
__device__ __forceinline__ void mma_f8(float* c, uint32_t a0, uint32_t a1, uint32_t a2,
                                       uint32_t a3, uint32_t b0, uint32_t b1) {
    asm volatile(
        "mma.sync.aligned.m16n8k32.row.col.f32.e4m3.e4m3.f32 "
        "{%0,%1,%2,%3}, {%4,%5,%6,%7}, {%8,%9}, {%0,%1,%2,%3};"
        : "+f"(c[0]), "+f"(c[1]), "+f"(c[2]), "+f"(c[3])
        : "r"(a0), "r"(a1), "r"(a2), "r"(a3), "r"(b0), "r"(b1));
}
__device__ __forceinline__ float hsum(uint32_t w) {
    __half2 h = *(__half2*)&w;
    float2 f = __half22float2(h);
    return f.x + f.y;
}
__device__ __forceinline__ uint16_t f2e4m3x2(float hi, float lo) {
    uint16_t u;
    asm("cvt.rn.satfinite.e4m3x2.f32 %0, %1, %2;" : "=h"(u) : "f"(hi), "f"(lo));
    return u;
}

// ---------------- fused prep (rows) + fp8 transpose, one launch ----------------
__global__ void prep_trans_kernel(const float* __restrict__ x) {
    int b = blockIdx.x;
    int t = threadIdx.x;  // 256
    if (b < 4096) {
        __shared__ float sred[8];
        int row = 2 * b + (t >> 7);
        int tt = t & 127;
        if (tt == 0) g_rsum[row] = 0.f;
        float4 a = ((const float4*)(x + (size_t)row * D))[tt];
        float ss = a.x * a.x + a.y * a.y + a.z * a.z + a.w * a.w;
        ss = warpReduceSum(ss);
        if ((t & 31) == 0) sred[t >> 5] = ss;
        __syncthreads();
        int base = (t >> 7) * 4;
        float tot = sred[base] + sred[base + 1] + sred[base + 2] + sred[base + 3];
        float inv = 1.0f / fmaxf(sqrtf(tot), 1e-12f);
        float v[4] = {a.x * inv, a.y * inv, a.z * inv, a.w * inv};
        __half2* dst = (__half2*)(g_xnh + (size_t)row * D);
#pragma unroll
        for (int e = 0; e < 2; e++) {
            int w = 2 * tt + e;  // logical word
            int wg = w & 7;
            int sp = (w & ~7) | (2 * (wg & 3) + (wg >> 2));
            dst[sp] = __floats2half2_rn(v[2 * e], v[2 * e + 1]);
        }
    } else {
        __shared__ float tl[32][33];
        int id = b - 4096;
        int k0 = (id & 255) * 32, n0 = (id >> 8) * 32;
        int tx = t & 31, ty = t >> 5;  // 32 x 8
#pragma unroll
        for (int r = 0; r < 32; r += 8)
            tl[ty + r][tx] = x[(size_t)(k0 + ty + r) * D + n0 + tx];
        __syncthreads();
        // stored byte tx (within 32-byte group) holds logical byte lb
        int p = tx >> 2;
        int lb = 4 * lword(p) + (tx & 3);
#pragma unroll
        for (int r = 0; r < 32; r += 8) {
            uint16_t u = f2e4m3x2(0.f, tl[lb][ty + r]);
            g_xt8[(size_t)(n0 + ty + r) * NR + k0 + tx] = (uint8_t)(u & 0xff);
        }
    }
}

// ============== GEMM1: E = exp(xn @ xn^T - 1) fp16, 128x128 tiles, triangular + mirror + rowsum ==============
__global__ void __launch_bounds__(256, 2) gemm1_kernel() {
    int kid = blockIdx.x;
    int bj = (int)((sqrtf(8.0f * (float)kid + 1.0f) - 1.0f) * 0.5f);
    while ((bj + 1) * (bj + 2) / 2 <= kid) bj++;
    while (bj * (bj + 1) / 2 > kid) bj--;
    int bi = kid - bj * (bj + 1) / 2;
    const int I0 = bi * 128, J0 = bj * 128;

    extern __shared__ uint32_t su[];
    uint32_t sbase = smem_u32(su);
    int t = threadIdx.x, wid = t >> 5, lane = t & 31;
    int g = lane >> 2, tq = lane & 3;
    int warpM = (wid >> 2) * 64, warpN = (wid & 3) * 32;

    const __half* aG = g_xnh + (size_t)(I0 + (t >> 1)) * D + (t & 1) * 32;
    const __half* bG = g_xnh + (size_t)(J0 + (t >> 1)) * D + (t & 1) * 32;
    uint32_t dstA = sbase + (uint32_t)((t >> 1) * ROWW + (t & 1) * 16) * 4;
    uint32_t dstB = sbase + (uint32_t)(A_TILE_W + (t >> 1) * ROWW + (t & 1) * 16) * 4;

    auto copy_stage = [&](int stage, int k0) {
        uint32_t off = (uint32_t)(stage * STAGE_W) * 4;
#pragma unroll
        for (int q = 0; q < 4; q++) {
            cp16(dstA + off + q * 16, aG + k0 + q * 8);
            cp16(dstB + off + q * 16, bG + k0 + q * 8);
        }
        CP_COMMIT();
    };

    float acc[4][4][4];
#pragma unroll
    for (int i = 0; i < 4; i++)
#pragma unroll
        for (int j = 0; j < 4; j++)
#pragma unroll
            for (int q = 0; q < 4; q++) acc[i][j][q] = 0.f;

    const int C = D / 64;  // 8 chunks
    copy_stage(0, 0);
    copy_stage(1, 64);

    for (int c = 0; c < C; c++) {
        if (c + 2 < C) CP_WAIT1(); else CP_WAIT0();
        __syncthreads();
        const uint32_t* sA = su + (c & 1) * STAGE_W;
        const uint32_t* sB = sA + A_TILE_W;
#pragma unroll
        for (int s = 0; s < 4; s++) {
            uint32_t af[4][4], bf[4][2];
#pragma unroll
            for (int i = 0; i < 4; i++) {
                const uint32_t* pa = sA + (warpM + i * 16 + g) * ROWW + 8 * s + 2 * tq;
                uint2 lo = *(const uint2*)pa;
                uint2 hi = *(const uint2*)(pa + 8 * ROWW);
                af[i][0] = lo.x; af[i][1] = hi.x; af[i][2] = lo.y; af[i][3] = hi.y;
            }
#pragma unroll
            for (int j = 0; j < 4; j++) {
                uint2 b = *(const uint2*)(sB + (warpN + j * 8 + g) * ROWW + 8 * s + 2 * tq);
                bf[j][0] = b.x; bf[j][1] = b.y;
            }
#pragma unroll
            for (int i = 0; i < 4; i++)
#pragma unroll
                for (int j = 0; j < 4; j++)
                    mma_f16(acc[i][j], af[i][0], af[i][1], af[i][2], af[i][3],
                            bf[j][0], bf[j][1]);
        }
        __syncthreads();
        if (c + 2 < C) copy_stage(c & 1, (c + 2) * 64);
    }
    __syncthreads();

    // ---- epilogue: exp(s-1) -> eb_w[128][67] half2 words -> permuted fp16 writes + rowsums ----
    const int EBW = 67;
    uint32_t* eb = su;
#pragma unroll
    for (int i = 0; i < 4; i++)
#pragma unroll
        for (int j = 0; j < 4; j++) {
            int r0 = warpM + i * 16 + g;
            int wrd = ((warpN + j * 8) >> 1) + tq;
            __half2 lo = __floats2half2_rn(__expf(acc[i][j][0] - 1.0f), __expf(acc[i][j][1] - 1.0f));
            __half2 hi = __floats2half2_rn(__expf(acc[i][j][2] - 1.0f), __expf(acc[i][j][3] - 1.0f));
            eb[r0 * EBW + wrd]       = *(uint32_t*)&lo;
            eb[(r0 + 8) * EBW + wrd] = *(uint32_t*)&hi;
        }
    __syncthreads();

    {
        int s0 = (lane >> 2) * 8 + (lane & 3);
#pragma unroll 1
        for (int it = 0; it < 16; it++) {
            int r = wid * 16 + it;
            const uint32_t* src = eb + r * EBW;
            uint2 v = make_uint2(src[s0], src[s0 + 4]);
            *(uint2*)(g_Eh + (size_t)(I0 + r) * NR + J0 + 4 * lane) = v;
            float fs = hsum(v.x) + hsum(v.y);
            fs = warpReduceSum(fs);
            if (lane == 0) atomicAdd(&g_rsum[I0 + r], fs);
        }
    }
    {
        bool addMirror = (bi != bj);
        int w = 8 * (lane >> 2) + (lane & 3);
        int r0 = 2 * w;
#pragma unroll 1
        for (int it = 0; it < 16; it++) {
            int cc = wid * 16 + it;
            int cw = cc >> 1, ch = (cc & 1) * 16;
            uint32_t h0 = (eb[(r0)     * EBW + cw] >> ch) & 0xffffu;
            uint32_t h1 = (eb[(r0 + 1) * EBW + cw] >> ch) & 0xffffu;
            uint32_t h2 = (eb[(r0 + 8) * EBW + cw] >> ch) & 0xffffu;
            uint32_t h3 = (eb[(r0 + 9) * EBW + cw] >> ch) & 0xffffu;
            uint2 v = make_uint2(h0 | (h1 << 16), h2 | (h3 << 16));
            *(uint2*)(g_Eh + (size_t)(J0 + cc) * NR + I0 + 4 * lane) = v;
            if (addMirror) {
                float fs = hsum(v.x) + hsum(v.y);
                fs = warpReduceSum(fs);
                if (lane == 0) atomicAdd(&g_rsum[J0 + cc], fs);
            }
        }
    }
}

// ---------------- invr: 1/rsum ----------------
__global__ void invr_kernel() {
    int i = blockIdx.x * 256 + threadIdx.x;
    g_invr[i] = 1.0f / g_rsum[i];
}

// ---------------- scale8: A8 = e4m3(E*(invr_i+invr_j)*4096), byte-permuted ----------------
__global__ void scale8_kernel() {
    int row = blockIdx.x, t = threadIdx.x;  // 256 threads, 32 k each
    float ri = g_invr[row];
    const uint4* src = (const uint4*)(g_Eh + (size_t)row * NR + 32 * t);
    __half hv[32];
    *(uint4*)(hv)      = src[0];
    *(uint4*)(hv + 8)  = src[1];
    *(uint4*)(hv + 16) = src[2];
    *(uint4*)(hv + 24) = src[3];
    float rj[32];
    const float4* rp = (const float4*)(g_invr + 32 * t);
#pragma unroll
    for (int q = 0; q < 8; q++) {
        float4 v = __ldg(rp + q);
        rj[4 * q] = v.x; rj[4 * q + 1] = v.y; rj[4 * q + 2] = v.z; rj[4 * q + 3] = v.w;
    }
    float av[32];  // logical order values, scaled
#pragma unroll
    for (int u = 0; u < 32; u++) {
        int g16 = u >> 4, uu = u & 15, w = uu >> 1, e = uu & 1;
        int sw = 2 * (w & 3) + (w >> 2);  // logical word w stored at 2(w&3)+(w>>2)
        int sh = g16 * 16 + sw * 2 + e;
        av[u] = __half2float(hv[sh]) * ((ri + rj[u]) * A8SCALE);
    }
    uint16_t pk[16];
#pragma unroll
    for (int m = 0; m < 16; m++) {
        int sb0 = 2 * m, sb1 = 2 * m + 1;
        int p0 = sb0 >> 2, lb0 = 4 * lword(p0) + (sb0 & 3);
        int p1 = sb1 >> 2, lb1 = 4 * lword(p1) + (sb1 & 3);
        pk[m] = f2e4m3x2(av[lb1], av[lb0]);  // hi byte = first operand
    }
    const uint32_t* pw = (const uint32_t*)pk;
    uint4* dst = (uint4*)(g_A8 + (size_t)row * NR + 32 * t);
    dst[0] = make_uint4(pw[0], pw[1], pw[2], pw[3]);
    dst[1] = make_uint4(pw[4], pw[5], pw[6], pw[7]);
}

// ============== GEMM2 (fp8): xneg = A8 @ x8 / 4096, 128x256 tiles, 3-stage, pure cp.async ==============
__global__ void __launch_bounds__(256, 1) gemm2_kernel() {
    const int n0 = blockIdx.x * 256;  // 0..1
    const int I0 = blockIdx.y * 128;  // 0..63

    extern __shared__ uint32_t su[];
    uint32_t sbase = smem_u32(su);
    int t = threadIdx.x, wid = t >> 5, lane = t & 31;
    int g = lane >> 2, tq = lane & 3;
    int warpM = (wid >> 2) * 64, warpN = (wid & 3) * 64;

    const uint8_t* aG = g_A8 + (size_t)(I0 + (t >> 1)) * NR + (t & 1) * 32;
    const uint8_t* bG = g_xt8 + (size_t)(n0 + t) * NR;
    uint32_t dstA = sbase + (uint32_t)((t >> 1) * F8_ROWW + (t & 1) * 8) * 4;
    uint32_t dstB = sbase + (uint32_t)(F8_A_W + t * F8_ROWW) * 4;

    auto copy_stage = [&](int stg, int k0) {
        uint32_t off = (uint32_t)(stg * F8_STAGE_W) * 4;
        cp16(dstA + off, aG + k0);
        cp16(dstA + off + 16, aG + k0 + 16);
#pragma unroll
        for (int q = 0; q < 4; q++) cp16(dstB + off + q * 16, bG + k0 + q * 16);
        CP_COMMIT();
    };

    float acc[4][8][4];
#pragma unroll
    for (int i = 0; i < 4; i++)
#pragma unroll
        for (int j = 0; j < 8; j++)
#pragma unroll
            for (int q = 0; q < 4; q++) acc[i][j][q] = 0.f;

    const int C = NR / 64;  // 128 chunks of 64 k-bytes
    copy_stage(0, 0);
    copy_stage(1, 64);

    int stage = 0;
    for (int c = 0; c < C; c++) {
        if (c + 2 < C) CP_WAIT1(); else CP_WAIT0();
        __syncthreads();
        if (c + 2 < C) {
            int ns = stage + 2; if (ns >= 3) ns -= 3;
            copy_stage(ns, (c + 2) * 64);
        }
        const uint32_t* sA = su + stage * F8_STAGE_W;
        const uint32_t* sB = sA + F8_A_W;
#pragma unroll
        for (int s = 0; s < 2; s++) {  // 2 k32 steps per 64-byte chunk
            uint32_t af[4][4], bf[8][2];
#pragma unroll
            for (int i = 0; i < 4; i++) {
                const uint32_t* pa = sA + (warpM + i * 16 + g) * F8_ROWW + 8 * s + 2 * tq;
                uint2 lo = *(const uint2*)pa;                  // (a0, a2)
                uint2 hi = *(const uint2*)(pa + 8 * F8_ROWW);  // (a1, a3)
                af[i][0] = lo.x; af[i][1] = hi.x; af[i][2] = lo.y; af[i][3] = hi.y;
            }
#pragma unroll
            for (int j = 0; j < 8; j++) {
                uint2 b = *(const uint2*)(sB + (warpN + j * 8 + g) * F8_ROWW + 8 * s + 2 * tq);
                bf[j][0] = b.x; bf[j][1] = b.y;
            }
#pragma unroll
            for (int i = 0; i < 4; i++)
#pragma unroll
                for (int j = 0; j < 8; j++)
                    mma_f8(acc[i][j], af[i][0], af[i][1], af[i][2], af[i][3],
                           bf[j][0], bf[j][1]);
        }
        if (++stage >= 3) stage = 0;
    }

    // epilogue: undo A8SCALE, f32 stores
    const float is = 1.0f / A8SCALE;
#pragma unroll
    for (int i = 0; i < 4; i++)
#pragma unroll
        for (int j = 0; j < 8; j++) {
            int r0 = I0 + warpM + i * 16 + g;
            int c0 = n0 + warpN + j * 8 + 2 * tq;
            *(float2*)(g_xneg + (size_t)r0 * D + c0) =
                make_float2(acc[i][j][0] * is, acc[i][j][1] * is);
            *(float2*)(g_xneg + (size_t)(r0 + 8) * D + c0) =
                make_float2(acc[i][j][2] * is, acc[i][j][3] * is);
        }
}

// ---------------- y = x - SCALE*xneg, LayerNorm ----------------
__global__ void ln_kernel(const float* __restrict__ x, const float* __restrict__ gamma,
                          const float* __restrict__ beta, float* __restrict__ out) {
    __shared__ float s1[4], s2[4];
    int row = blockIdx.x, t = threadIdx.x;  // 128 threads
    float4 xv = ((const float4*)(x + (size_t)row * D))[t];
    float4 nv = ((const float4*)(g_xneg + (size_t)row * D))[t];
    float4 y = make_float4(xv.x - SCALEF * nv.x, xv.y - SCALEF * nv.y,
                           xv.z - SCALEF * nv.z, xv.w - SCALEF * nv.w);
    float s = y.x + y.y + y.z + y.w;
    float q = y.x * y.x + y.y * y.y + y.z * y.z + y.w * y.w;
    s = warpReduceSum(s);
    q = warpReduceSum(q);
    if ((t & 31) == 0) { s1[t >> 5] = s; s2[t >> 5] = q; }
    __syncthreads();
    float sum = s1[0] + s1[1] + s1[2] + s1[3];
    float sq  = s2[0] + s2[1] + s2[2] + s2[3];
    float mean = sum * (1.0f / D);
    float var = sq * (1.0f / D) - mean * mean;
    float rstd = rsqrtf(var + 1e-6f);
    float4 gm = ((const float4*)gamma)[t];
    float4 b = ((const float4*)beta)[t];
    float4 o;
    o.x = (y.x - mean) * rstd * gm.x + b.x;
    o.y = (y.y - mean) * rstd * gm.y + b.y;
    o.z = (y.z - mean) * rstd * gm.z + b.z;
    o.w = (y.w - mean) * rstd * gm.w + b.w;
    ((float4*)out)[(size_t)row * (D / 4) + t] = o;
}

extern "C" void kernel_launch(void* const* d_in, const int* in_sizes, int n_in,
                              void* d_out, int out_size) {
    const float* x     = (const float*)d_in[0];
    const float* gamma = (const float*)d_in[1];
    const float* beta  = (const float*)d_in[2];
    float* out = (float*)d_out;

    cudaFuncSetAttribute(gemm1_kernel, cudaFuncAttributeMaxDynamicSharedMemorySize, SMEM_BYTES);
    cudaFuncSetAttribute(gemm2_kernel, cudaFuncAttributeMaxDynamicSharedMemorySize, F8_SMEM);

    prep_trans_kernel<<<8192, 256>>>(x);
    gemm1_kernel<<<64 * 65 / 2, 256, SMEM_BYTES>>>();
    invr_kernel<<<NR / 256, 256>>>();
    scale8_kernel<<<NR, 256>>>();
    gemm2_kernel<<<dim3(2, 64), 256, F8_SMEM>>>();
    ln_kernel<<<NR, 128>>>(x, gamma, beta, out);
}

// round 17
// speedup vs baseline: 1.5059x; 1.1673x over previous
#include <cuda_runtime.h>
#include <cuda_fp16.h>
#include <math.h>
#include <stdint.h>

#define NR 8192
#define D  512
#define SCALEF 0.1f
#define A8SCALE 4096.0f
#define XNSCALE 16.0f           // xn quant scale; sim = acc/256

__device__ __half   g_Eh[(size_t)NR * NR];   // 128 MB: E fp16, k-word-permuted columns
__device__ uint8_t  g_A8[(size_t)NR * NR];   // 64 MB: e4m3 of E*(invr_i+invr_j)*4096, byte-permuted
__device__ uint8_t  g_xn8[(size_t)NR * D];   // xn e4m3 (x16), byte-permuted features
__device__ uint8_t  g_xt8[(size_t)D * NR];   // x^T e4m3 [512][8192], byte-permuted columns
__device__ float    g_xneg[(size_t)NR * D];
__device__ float    g_rsum[NR];
__device__ float    g_invr[NR];              // natural order

// word perm within 8-word groups: stored word p holds logical word l(p) = (p>>1) + 4*(p&1)
__device__ __host__ __forceinline__ int lword(int p) { return (p >> 1) + 4 * (p & 1); }

// ---- fp8 GEMM smem config ----
#define F8_ROWW 24                        // 16 data words + 8 pad (conflict-free LDS.64 phases)
// gemm1: 128x128 tiles, 2-stage
#define G1_A_W (128 * F8_ROWW)            // 3072
#define G1_STAGE_W (2 * G1_A_W)           // 6144 words = 24 KB
#define G1_SMEM (2 * G1_STAGE_W * 4)      // 49152 -> 2 CTA/SM; epilogue needs 128*67*4=34304 < 49152
// gemm2: 128x256 tiles, 3-stage
#define F8_A_W (128 * F8_ROWW)            // 3072
#define F8_B_W (256 * F8_ROWW)            // 6144
#define F8_STAGE_W (F8_A_W + F8_B_W)      // 9216 words = 36 KB
#define F8_SMEM (3 * F8_STAGE_W * 4)      // 110592

__device__ __forceinline__ float warpReduceSum(float v) {
#pragma unroll
    for (int o = 16; o > 0; o >>= 1) v += __shfl_xor_sync(0xffffffffu, v, o);
    return v;
}
__device__ __forceinline__ uint32_t smem_u32(const void* p) {
    uint32_t a;
    asm("{ .reg .u64 t; cvta.to.shared.u64 t, %1; cvt.u32.u64 %0, t; }" : "=r"(a) : "l"(p));
    return a;
}
__device__ __forceinline__ void cp16(uint32_t s, const void* g) {
    asm volatile("cp.async.cg.shared.global [%0], [%1], 16;" :: "r"(s), "l"(g));
}
#define CP_COMMIT() asm volatile("cp.async.commit_group;")
#define CP_WAIT1()  asm volatile("cp.async.wait_group 1;")
#define CP_WAIT0()  asm volatile("cp.async.wait_group 0;")

__device__ __forceinline__ void mma_f8(float* c, uint32_t a0, uint32_t a1, uint32_t a2,
                                       uint32_t a3, uint32_t b0, uint32_t b1) {
    asm volatile(
        "mma.sync.aligned.m16n8k32.row.col.f32.e4m3.e4m3.f32 "
        "{%0,%1,%2,%3}, {%4,%5,%6,%7}, {%8,%9}, {%0,%1,%2,%3};"
        : "+f"(c[0]), "+f"(c[1]), "+f"(c[2]), "+f"(c[3])
        : "r"(a0), "r"(a1), "r"(a2), "r"(a3), "r"(b0), "r"(b1));
}
__device__ __forceinline__ float hsum(uint32_t w) {
    __half2 h = *(__half2*)&w;
    float2 f = __half22float2(h);
    return f.x + f.y;
}
__device__ __forceinline__ uint16_t f2e4m3x2(float hi, float lo) {
    uint16_t u;
    asm("cvt.rn.satfinite.e4m3x2.f32 %0, %1, %2;" : "=h"(u) : "f"(hi), "f"(lo));
    return u;
}

// ---------------- fused prep (rows -> xn8) + fp8 transpose, one launch ----------------
__global__ void prep_trans_kernel(const float* __restrict__ x) {
    int b = blockIdx.x;
    int t = threadIdx.x;  // 256
    if (b < 4096) {
        __shared__ float sred[8];
        int row = 2 * b + (t >> 7);
        int tt = t & 127;
        if (tt == 0) g_rsum[row] = 0.f;
        float4 a = ((const float4*)(x + (size_t)row * D))[tt];
        float ss = a.x * a.x + a.y * a.y + a.z * a.z + a.w * a.w;
        ss = warpReduceSum(ss);
        if ((t & 31) == 0) sred[t >> 5] = ss;
        __syncthreads();
        int base = (t >> 7) * 4;
        float tot = sred[base] + sred[base + 1] + sred[base + 2] + sred[base + 3];
        float inv = XNSCALE / fmaxf(sqrtf(tot), 1e-12f);
        // logical word tt -> stored word position within 8-word group
        int w8 = tt & 7;
        int sw = (tt & ~7) | (2 * (w8 & 3) + (w8 >> 2));
        uint32_t lo = f2e4m3x2(a.y * inv, a.x * inv);
        uint32_t hi = f2e4m3x2(a.w * inv, a.z * inv);
        ((uint32_t*)(g_xn8 + (size_t)row * D))[sw] = lo | (hi << 16);
    } else {
        __shared__ float tl[32][33];
        int id = b - 4096;
        int k0 = (id & 255) * 32, n0 = (id >> 8) * 32;
        int tx = t & 31, ty = t >> 5;  // 32 x 8
#pragma unroll
        for (int r = 0; r < 32; r += 8)
            tl[ty + r][tx] = x[(size_t)(k0 + ty + r) * D + n0 + tx];
        __syncthreads();
        int p = tx >> 2;
        int lb = 4 * lword(p) + (tx & 3);
#pragma unroll
        for (int r = 0; r < 32; r += 8) {
            uint16_t u = f2e4m3x2(0.f, tl[lb][ty + r]);
            g_xt8[(size_t)(n0 + ty + r) * NR + k0 + tx] = (uint8_t)(u & 0xff);
        }
    }
}

// ============== GEMM1 (fp8): E = exp((xn8@xn8^T)/256 - 1), 128x128 triangular + mirror + rowsum ==============
__global__ void __launch_bounds__(256, 2) gemm1_kernel() {
    int kid = blockIdx.x;
    int bj = (int)((sqrtf(8.0f * (float)kid + 1.0f) - 1.0f) * 0.5f);
    while ((bj + 1) * (bj + 2) / 2 <= kid) bj++;
    while (bj * (bj + 1) / 2 > kid) bj--;
    int bi = kid - bj * (bj + 1) / 2;
    const int I0 = bi * 128, J0 = bj * 128;

    extern __shared__ uint32_t su[];
    uint32_t sbase = smem_u32(su);
    int t = threadIdx.x, wid = t >> 5, lane = t & 31;
    int g = lane >> 2, tq = lane & 3;
    int warpM = (wid >> 2) * 64, warpN = (wid & 3) * 32;

    const uint8_t* aG = g_xn8 + (size_t)(I0 + (t >> 1)) * D + (t & 1) * 32;
    const uint8_t* bG = g_xn8 + (size_t)(J0 + (t >> 1)) * D + (t & 1) * 32;
    uint32_t dstA = sbase + (uint32_t)((t >> 1) * F8_ROWW + (t & 1) * 8) * 4;
    uint32_t dstB = sbase + (uint32_t)(G1_A_W + (t >> 1) * F8_ROWW + (t & 1) * 8) * 4;

    auto copy_stage = [&](int stage, int k0) {
        uint32_t off = (uint32_t)(stage * G1_STAGE_W) * 4;
        cp16(dstA + off, aG + k0);
        cp16(dstA + off + 16, aG + k0 + 16);
        cp16(dstB + off, bG + k0);
        cp16(dstB + off + 16, bG + k0 + 16);
        CP_COMMIT();
    };

    float acc[4][4][4];
#pragma unroll
    for (int i = 0; i < 4; i++)
#pragma unroll
        for (int j = 0; j < 4; j++)
#pragma unroll
            for (int q = 0; q < 4; q++) acc[i][j][q] = 0.f;

    const int C = D / 64;  // 8 chunks of 64 k-bytes
    copy_stage(0, 0);
    copy_stage(1, 64);

    for (int c = 0; c < C; c++) {
        if (c + 2 < C) CP_WAIT1(); else CP_WAIT0();
        __syncthreads();
        const uint32_t* sA = su + (c & 1) * G1_STAGE_W;
        const uint32_t* sB = sA + G1_A_W;
#pragma unroll
        for (int s = 0; s < 2; s++) {  // 2 k32 steps per chunk
            uint32_t af[4][4], bf[4][2];
#pragma unroll
            for (int i = 0; i < 4; i++) {
                const uint32_t* pa = sA + (warpM + i * 16 + g) * F8_ROWW + 8 * s + 2 * tq;
                uint2 lo = *(const uint2*)pa;
                uint2 hi = *(const uint2*)(pa + 8 * F8_ROWW);
                af[i][0] = lo.x; af[i][1] = hi.x; af[i][2] = lo.y; af[i][3] = hi.y;
            }
#pragma unroll
            for (int j = 0; j < 4; j++) {
                uint2 b = *(const uint2*)(sB + (warpN + j * 8 + g) * F8_ROWW + 8 * s + 2 * tq);
                bf[j][0] = b.x; bf[j][1] = b.y;
            }
#pragma unroll
            for (int i = 0; i < 4; i++)
#pragma unroll
                for (int j = 0; j < 4; j++)
                    mma_f8(acc[i][j], af[i][0], af[i][1], af[i][2], af[i][3],
                           bf[j][0], bf[j][1]);
        }
        __syncthreads();
        if (c + 2 < C) copy_stage(c & 1, (c + 2) * 64);
    }
    __syncthreads();

    // ---- epilogue: exp(acc/256 - 1) -> eb_w[128][67] half2 words -> permuted fp16 writes + rowsums ----
    const int EBW = 67;
    const float SINV = 1.0f / (XNSCALE * XNSCALE);
    uint32_t* eb = su;
#pragma unroll
    for (int i = 0; i < 4; i++)
#pragma unroll
        for (int j = 0; j < 4; j++) {
            int r0 = warpM + i * 16 + g;
            int wrd = ((warpN + j * 8) >> 1) + tq;
            __half2 lo = __floats2half2_rn(__expf(acc[i][j][0] * SINV - 1.0f),
                                           __expf(acc[i][j][1] * SINV - 1.0f));
            __half2 hi = __floats2half2_rn(__expf(acc[i][j][2] * SINV - 1.0f),
                                           __expf(acc[i][j][3] * SINV - 1.0f));
            eb[r0 * EBW + wrd]       = *(uint32_t*)&lo;
            eb[(r0 + 8) * EBW + wrd] = *(uint32_t*)&hi;
        }
    __syncthreads();

    {
        int s0 = (lane >> 2) * 8 + (lane & 3);
#pragma unroll 1
        for (int it = 0; it < 16; it++) {
            int r = wid * 16 + it;
            const uint32_t* src = eb + r * EBW;
            uint2 v = make_uint2(src[s0], src[s0 + 4]);
            *(uint2*)(g_Eh + (size_t)(I0 + r) * NR + J0 + 4 * lane) = v;
            float fs = hsum(v.x) + hsum(v.y);
            fs = warpReduceSum(fs);
            if (lane == 0) atomicAdd(&g_rsum[I0 + r], fs);
        }
    }
    {
        bool addMirror = (bi != bj);
        int w = 8 * (lane >> 2) + (lane & 3);
        int r0 = 2 * w;
#pragma unroll 1
        for (int it = 0; it < 16; it++) {
            int cc = wid * 16 + it;
            int cw = cc >> 1, ch = (cc & 1) * 16;
            uint32_t h0 = (eb[(r0)     * EBW + cw] >> ch) & 0xffffu;
            uint32_t h1 = (eb[(r0 + 1) * EBW + cw] >> ch) & 0xffffu;
            uint32_t h2 = (eb[(r0 + 8) * EBW + cw] >> ch) & 0xffffu;
            uint32_t h3 = (eb[(r0 + 9) * EBW + cw] >> ch) & 0xffffu;
            uint2 v = make_uint2(h0 | (h1 << 16), h2 | (h3 << 16));
            *(uint2*)(g_Eh + (size_t)(J0 + cc) * NR + I0 + 4 * lane) = v;
            if (addMirror) {
                float fs = hsum(v.x) + hsum(v.y);
                fs = warpReduceSum(fs);
                if (lane == 0) atomicAdd(&g_rsum[J0 + cc], fs);
            }
        }
    }
}

// ---------------- invr: 1/rsum ----------------
__global__ void invr_kernel() {
    int i = blockIdx.x * 256 + threadIdx.x;
    g_invr[i] = 1.0f / g_rsum[i];
}

// ---------------- scale8 v2: 8 rows/block, rj cached in registers ----------------
__global__ void scale8_kernel() {
    int rb = blockIdx.x * 8;        // 1024 blocks
    int t = threadIdx.x;            // 256 threads, k-slice [32t, 32t+32)
    float rj[32];
    const float4* rp = (const float4*)(g_invr + 32 * t);
#pragma unroll
    for (int q = 0; q < 8; q++) {
        float4 v = __ldg(rp + q);
        rj[4 * q] = v.x; rj[4 * q + 1] = v.y; rj[4 * q + 2] = v.z; rj[4 * q + 3] = v.w;
    }
#pragma unroll 1
    for (int r8 = 0; r8 < 8; r8++) {
        int row = rb + r8;
        float ri = __ldg(&g_invr[row]);
        const uint4* src = (const uint4*)(g_Eh + (size_t)row * NR + 32 * t);
        __half hv[32];
        *(uint4*)(hv)      = src[0];
        *(uint4*)(hv + 8)  = src[1];
        *(uint4*)(hv + 16) = src[2];
        *(uint4*)(hv + 24) = src[3];
        float av[32];  // logical order, scaled
#pragma unroll
        for (int u = 0; u < 32; u++) {
            int g16 = u >> 4, uu = u & 15, w = uu >> 1, e = uu & 1;
            int sw = 2 * (w & 3) + (w >> 2);
            int sh = g16 * 16 + sw * 2 + e;
            av[u] = __half2float(hv[sh]) * ((ri + rj[u]) * A8SCALE);
        }
        uint16_t pk[16];
#pragma unroll
        for (int m = 0; m < 16; m++) {
            int sb0 = 2 * m, sb1 = 2 * m + 1;
            int p0 = sb0 >> 2, lb0 = 4 * lword(p0) + (sb0 & 3);
            int p1 = sb1 >> 2, lb1 = 4 * lword(p1) + (sb1 & 3);
            pk[m] = f2e4m3x2(av[lb1], av[lb0]);
        }
        const uint32_t* pw = (const uint32_t*)pk;
        uint4* dst = (uint4*)(g_A8 + (size_t)row * NR + 32 * t);
        dst[0] = make_uint4(pw[0], pw[1], pw[2], pw[3]);
        dst[1] = make_uint4(pw[4], pw[5], pw[6], pw[7]);
    }
}

// ============== GEMM2 (fp8): xneg = A8 @ x8 / 4096, 128x256 tiles, 3-stage, pure cp.async ==============
__global__ void __launch_bounds__(256, 1) gemm2_kernel() {
    const int n0 = blockIdx.x * 256;  // 0..1
    const int I0 = blockIdx.y * 128;  // 0..63

    extern __shared__ uint32_t su[];
    uint32_t sbase = smem_u32(su);
    int t = threadIdx.x, wid = t >> 5, lane = t & 31;
    int g = lane >> 2, tq = lane & 3;
    int warpM = (wid >> 2) * 64, warpN = (wid & 3) * 64;

    const uint8_t* aG = g_A8 + (size_t)(I0 + (t >> 1)) * NR + (t & 1) * 32;
    const uint8_t* bG = g_xt8 + (size_t)(n0 + t) * NR;
    uint32_t dstA = sbase + (uint32_t)((t >> 1) * F8_ROWW + (t & 1) * 8) * 4;
    uint32_t dstB = sbase + (uint32_t)(F8_A_W + t * F8_ROWW) * 4;

    auto copy_stage = [&](int stg, int k0) {
        uint32_t off = (uint32_t)(stg * F8_STAGE_W) * 4;
        cp16(dstA + off, aG + k0);
        cp16(dstA + off + 16, aG + k0 + 16);
#pragma unroll
        for (int q = 0; q < 4; q++) cp16(dstB + off + q * 16, bG + k0 + q * 16);
        CP_COMMIT();
    };

    float acc[4][8][4];
#pragma unroll
    for (int i = 0; i < 4; i++)
#pragma unroll
        for (int j = 0; j < 8; j++)
#pragma unroll
            for (int q = 0; q < 4; q++) acc[i][j][q] = 0.f;

    const int C = NR / 64;  // 128 chunks of 64 k-bytes
    copy_stage(0, 0);
    copy_stage(1, 64);

    int stage = 0;
    for (int c = 0; c < C; c++) {
        if (c + 2 < C) CP_WAIT1(); else CP_WAIT0();
        __syncthreads();
        if (c + 2 < C) {
            int ns = stage + 2; if (ns >= 3) ns -= 3;
            copy_stage(ns, (c + 2) * 64);
        }
        const uint32_t* sA = su + stage * F8_STAGE_W;
        const uint32_t* sB = sA + F8_A_W;
#pragma unroll
        for (int s = 0; s < 2; s++) {
            uint32_t af[4][4], bf[8][2];
#pragma unroll
            for (int i = 0; i < 4; i++) {
                const uint32_t* pa = sA + (warpM + i * 16 + g) * F8_ROWW + 8 * s + 2 * tq;
                uint2 lo = *(const uint2*)pa;
                uint2 hi = *(const uint2*)(pa + 8 * F8_ROWW);
                af[i][0] = lo.x; af[i][1] = hi.x; af[i][2] = lo.y; af[i][3] = hi.y;
            }
#pragma unroll
            for (int j = 0; j < 8; j++) {
                uint2 b = *(const uint2*)(sB + (warpN + j * 8 + g) * F8_ROWW + 8 * s + 2 * tq);
                bf[j][0] = b.x; bf[j][1] = b.y;
            }
#pragma unroll
            for (int i = 0; i < 4; i++)
#pragma unroll
                for (int j = 0; j < 8; j++)
                    mma_f8(acc[i][j], af[i][0], af[i][1], af[i][2], af[i][3],
                           bf[j][0], bf[j][1]);
        }
        if (++stage >= 3) stage = 0;
    }

    const float is = 1.0f / A8SCALE;
#pragma unroll
    for (int i = 0; i < 4; i++)
#pragma unroll
        for (int j = 0; j < 8; j++) {
            int r0 = I0 + warpM + i * 16 + g;
            int c0 = n0 + warpN + j * 8 + 2 * tq;
            *(float2*)(g_xneg + (size_t)r0 * D + c0) =
                make_float2(acc[i][j][0] * is, acc[i][j][1] * is);
            *(float2*)(g_xneg + (size_t)(r0 + 8) * D + c0) =
                make_float2(acc[i][j][2] * is, acc[i][j][3] * is);
        }
}

// ---------------- y = x - SCALE*xneg, LayerNorm ----------------
__global__ void ln_kernel(const float* __restrict__ x, const float* __restrict__ gamma,
                          const float* __restrict__ beta, float* __restrict__ out) {
    __shared__ float s1[4], s2[4];
    int row = blockIdx.x, t = threadIdx.x;  // 128 threads
    float4 xv = ((const float4*)(x + (size_t)row * D))[t];
    float4 nv = ((const float4*)(g_xneg + (size_t)row * D))[t];
    float4 y = make_float4(xv.x - SCALEF * nv.x, xv.y - SCALEF * nv.y,
                           xv.z - SCALEF * nv.z, xv.w - SCALEF * nv.w);
    float s = y.x + y.y + y.z + y.w;
    float q = y.x * y.x + y.y * y.y + y.z * y.z + y.w * y.w;
    s = warpReduceSum(s);
    q = warpReduceSum(q);
    if ((t & 31) == 0) { s1[t >> 5] = s; s2[t >> 5] = q; }
    __syncthreads();
    float sum = s1[0] + s1[1] + s1[2] + s1[3];
    float sq  = s2[0] + s2[1] + s2[2] + s2[3];
    float mean = sum * (1.0f / D);
    float var = sq * (1.0f / D) - mean * mean;
    float rstd = rsqrtf(var + 1e-6f);
    float4 gm = ((const float4*)gamma)[t];
    float4 b = ((const float4*)beta)[t];
    float4 o;
    o.x = (y.x - mean) * rstd * gm.x + b.x;
    o.y = (y.y - mean) * rstd * gm.y + b.y;
    o.z = (y.z - mean) * rstd * gm.z + b.z;
    o.w = (y.w - mean) * rstd * gm.w + b.w;
    ((float4*)out)[(size_t)row * (D / 4) + t] = o;
}

extern "C" void kernel_launch(void* const* d_in, const int* in_sizes, int n_in,
                              void* d_out, int out_size) {
    const float* x     = (const float*)d_in[0];
    const float* gamma = (const float*)d_in[1];
    const float* beta  = (const float*)d_in[2];
    float* out = (float*)d_out;

    cudaFuncSetAttribute(gemm1_kernel, cudaFuncAttributeMaxDynamicSharedMemorySize, G1_SMEM);
    cudaFuncSetAttribute(gemm2_kernel, cudaFuncAttributeMaxDynamicSharedMemorySize, F8_SMEM);

    prep_trans_kernel<<<8192, 256>>>(x);
    gemm1_kernel<<<64 * 65 / 2, 256, G1_SMEM>>>();
    invr_kernel<<<NR / 256, 256>>>();
    scale8_kernel<<<1024, 256>>>();
    gemm2_kernel<<<dim3(2, 64), 256, F8_SMEM>>>();
    ln_kernel<<<NR, 128>>>(x, gamma, beta, out);
}